// round 1
// baseline (speedup 1.0000x reference)
#include <cuda_runtime.h>

#define NMAX 50000
#define HID 128

// ---------------- scratch (no allocations allowed) ----------------
__device__ float g_bufA[NMAX * HID];
__device__ float g_bufB[NMAX * HID];
__device__ float g_mask[NMAX];
__device__ float g_colsum[HID];
__device__ float g_colsq[HID];
__device__ float g_bnscale[2][HID];
__device__ float g_bnshift[2][HID];

// ---------------- f32x2 helpers (Blackwell packed fp32) ----------------
__device__ __forceinline__ unsigned long long pack2(float x, float y) {
    unsigned long long r;
    asm("mov.b64 %0, {%1, %2};" : "=l"(r) : "f"(x), "f"(y));
    return r;
}
__device__ __forceinline__ void fma2(unsigned long long& c, unsigned long long a,
                                     unsigned long long b) {
    asm("fma.rn.f32x2 %0, %1, %2, %0;" : "+l"(c) : "l"(a), "l"(b));
}
__device__ __forceinline__ float2 unpack2(unsigned long long v) {
    float2 r;
    asm("mov.b64 {%0, %1}, %2;" : "=f"(r.x), "=f"(r.y) : "l"(v));
    return r;
}

// ---------------- small kernels ----------------
__global__ void k_init(float* mask, int n) {
    int i = blockIdx.x * blockDim.x + threadIdx.x;
    if (i < n) mask[i] = 0.f;
    if (i < HID) { g_colsum[i] = 0.f; g_colsq[i] = 0.f; }
}

__global__ void k_scatter(const int* __restrict__ dst, int E, float* __restrict__ mask) {
    int e = blockIdx.x * blockDim.x + threadIdx.x;
    if (e < E) mask[dst[e]] = 1.0f;
}

// column mean / mean-of-squares accumulation over y[n, 128]
__global__ void k_colstats(const float* __restrict__ y, int n) {
    __shared__ float s1[256], s2[256];
    int col = threadIdx.x & 127;
    int part = threadIdx.x >> 7;      // 0 or 1
    int base = blockIdx.x * 256;
    float a = 0.f, b = 0.f;
    for (int i = part; i < 256; i += 2) {
        int r = base + i;
        if (r < n) {
            float v = y[r * HID + col];
            a += v;
            b += v * v;
        }
    }
    s1[threadIdx.x] = a;
    s2[threadIdx.x] = b;
    __syncthreads();
    if (threadIdx.x < 128) {
        atomicAdd(&g_colsum[col], s1[threadIdx.x] + s1[threadIdx.x + 128]);
        atomicAdd(&g_colsq[col], s2[threadIdx.x] + s2[threadIdx.x + 128]);
    }
}

// turn stats into BN scale/shift (training-mode biased variance, eps=1e-5)
__global__ void k_finalize(const float* __restrict__ g, const float* __restrict__ beta,
                           int idx, int n) {
    int c = threadIdx.x;  // 128 threads
    float inv = 1.0f / (float)n;
    float mean = g_colsum[c] * inv;
    float var = g_colsq[c] * inv - mean * mean;
    float sc = g[c] * rsqrtf(var + 1e-5f);
    g_bnscale[idx][c] = sc;
    g_bnshift[idx][c] = beta[c] - sc * mean;
    g_colsum[c] = 0.f;
    g_colsq[c] = 0.f;
}

// ---------------- main GEMM: out[n,128] = op(A)[n,K] @ W[K,128] + bias ----------------
// PRO: 0 = raw A load, 1 = relu(bnscale*A + bnshift) applied on load (per feature k)
// EPI: 0 = none, 1 = relu, 2 = multiply by row mask
template <int K, int PRO, int EPI>
__global__ void __launch_bounds__(256, 2)
k_gemm(const float* __restrict__ A, const float* __restrict__ W,
       const float* __restrict__ bias, float* __restrict__ out, int n, int bnIdx,
       const float* __restrict__ maskf) {
    __shared__ __align__(16) float As[2][16][132];  // [stage][k][m], padded
    __shared__ __align__(16) float Bs[2][16][128];  // [stage][k][n]

    const int tid = threadIdx.x;
    const int tn = tid & 15;   // 0..15 -> col pairs
    const int tm = tid >> 4;   // 0..15 -> row groups of 8
    const int rowBase = blockIdx.x * 128;

    unsigned long long acc[8][4];
#pragma unroll
    for (int i = 0; i < 8; i++)
#pragma unroll
        for (int j = 0; j < 4; j++) acc[i][j] = 0ull;

    float4 aReg[2], bReg[2];

    auto loadG = [&](int k0) {
#pragma unroll
        for (int it = 0; it < 2; it++) {
            int f4 = tid + 256 * it;
            int r = f4 >> 2;           // 0..127 row within tile
            int kk = (f4 & 3) << 2;    // 0,4,8,12 within BK
            int row = rowBase + r;
            float4 v = make_float4(0.f, 0.f, 0.f, 0.f);
            if (row < n) v = *(const float4*)(A + row * K + k0 + kk);
            if (PRO == 1) {
                const float* sc = g_bnscale[bnIdx];
                const float* sh = g_bnshift[bnIdx];
                v.x = fmaxf(fmaf(sc[k0 + kk + 0], v.x, sh[k0 + kk + 0]), 0.f);
                v.y = fmaxf(fmaf(sc[k0 + kk + 1], v.y, sh[k0 + kk + 1]), 0.f);
                v.z = fmaxf(fmaf(sc[k0 + kk + 2], v.z, sh[k0 + kk + 2]), 0.f);
                v.w = fmaxf(fmaf(sc[k0 + kk + 3], v.w, sh[k0 + kk + 3]), 0.f);
            }
            aReg[it] = v;
        }
#pragma unroll
        for (int it = 0; it < 2; it++) {
            int f4 = tid + 256 * it;
            int kk = f4 >> 5;          // 0..15
            int nn = (f4 & 31) << 2;   // 0..124
            bReg[it] = *(const float4*)(W + (k0 + kk) * HID + nn);
        }
    };

    auto stsStage = [&](int s) {
#pragma unroll
        for (int it = 0; it < 2; it++) {
            int f4 = tid + 256 * it;
            int r = f4 >> 2;
            int kk = (f4 & 3) << 2;
            As[s][kk + 0][r] = aReg[it].x;
            As[s][kk + 1][r] = aReg[it].y;
            As[s][kk + 2][r] = aReg[it].z;
            As[s][kk + 3][r] = aReg[it].w;
            int kb = f4 >> 5;
            int nn = (f4 & 31) << 2;
            *(float4*)&Bs[s][kb][nn] = bReg[it];
        }
    };

    auto compute = [&](int s) {
#pragma unroll
        for (int k = 0; k < 16; k++) {
            float4 a0 = *(const float4*)&As[s][k][tm * 8];
            float4 a1 = *(const float4*)&As[s][k][tm * 8 + 4];
            unsigned long long aa[8];
            aa[0] = pack2(a0.x, a0.x);
            aa[1] = pack2(a0.y, a0.y);
            aa[2] = pack2(a0.z, a0.z);
            aa[3] = pack2(a0.w, a0.w);
            aa[4] = pack2(a1.x, a1.x);
            aa[5] = pack2(a1.y, a1.y);
            aa[6] = pack2(a1.z, a1.z);
            aa[7] = pack2(a1.w, a1.w);
#pragma unroll
            for (int j = 0; j < 4; j++) {
                unsigned long long b =
                    *(const unsigned long long*)&Bs[s][k][tn * 2 + 32 * j];
#pragma unroll
                for (int i = 0; i < 8; i++) fma2(acc[i][j], aa[i], b);
            }
        }
    };

    constexpr int KT = K / 16;
    loadG(0);
    stsStage(0);
    __syncthreads();
#pragma unroll 1
    for (int kt = 0; kt < KT; kt++) {
        if (kt + 1 < KT) loadG((kt + 1) * 16);
        compute(kt & 1);
        if (kt + 1 < KT) {
            stsStage((kt + 1) & 1);
            __syncthreads();
        }
    }

    // epilogue
#pragma unroll
    for (int i = 0; i < 8; i++) {
        int row = rowBase + tm * 8 + i;
        if (row < n) {
            float m = (EPI == 2) ? maskf[row] : 0.f;
#pragma unroll
            for (int j = 0; j < 4; j++) {
                int col = tn * 2 + 32 * j;
                float2 v = unpack2(acc[i][j]);
                v.x += bias[col];
                v.y += bias[col + 1];
                if (EPI == 1) { v.x = fmaxf(v.x, 0.f); v.y = fmaxf(v.y, 0.f); }
                if (EPI == 2) { v.x *= m; v.y *= m; }
                *(float2*)(out + row * HID + col) = v;
            }
        }
    }
}

// ---------------- launch ----------------
extern "C" void kernel_launch(void* const* d_in, const int* in_sizes, int n_in,
                              void* d_out, int out_size) {
    const float* x   = (const float*)d_in[0];
    const int*   ei  = (const int*)d_in[1];
    const float* W1  = (const float*)d_in[2];
    const float* b1  = (const float*)d_in[3];
    const float* g1  = (const float*)d_in[4];
    const float* be1 = (const float*)d_in[5];
    const float* W2  = (const float*)d_in[6];
    const float* b2  = (const float*)d_in[7];
    const float* g2  = (const float*)d_in[8];
    const float* be2 = (const float*)d_in[9];
    // d_in[10..13] = Wq,bq,Wk,bk : mathematically unused (softmax sums to 1)
    const float* Wv  = (const float*)d_in[14];
    const float* bv  = (const float*)d_in[15];
    const float* Wo  = (const float*)d_in[16];
    const float* bo  = (const float*)d_in[17];
    float* out = (float*)d_out;

    const int n = in_sizes[0] / 256;  // IN_DIM = 256
    const int E = in_sizes[1] / 2;
    const int* dst = ei + E;

    float *bufA, *bufB, *mask;
    cudaGetSymbolAddress((void**)&bufA, g_bufA);
    cudaGetSymbolAddress((void**)&bufB, g_bufB);
    cudaGetSymbolAddress((void**)&mask, g_mask);

    const int gblk = (n + 127) / 128;
    const int sblk = (n + 255) / 256;

    k_init<<<(n + 255) / 256, 256>>>(mask, n);
    k_scatter<<<(E + 255) / 256, 256>>>(dst, E, mask);

    // encoder layer 1: y1 = x @ W1 + b1 ; stats ; BN params #0
    k_gemm<256, 0, 0><<<gblk, 256>>>(x, W1, b1, bufA, n, 0, mask);
    k_colstats<<<sblk, 256>>>(bufA, n);
    k_finalize<<<1, 128>>>(g1, be1, 0, n);

    // encoder layer 2: y2 = relu(bn0(y1)) @ W2 + b2 ; stats ; BN params #1
    k_gemm<128, 1, 0><<<gblk, 256>>>(bufA, W2, b2, bufB, n, 0, mask);
    k_colstats<<<sblk, 256>>>(bufB, n);
    k_finalize<<<1, 128>>>(g2, be2, 1, n);

    // attn layer 0 (collapsed): z = mask * (relu(bn1(y2)) @ Wv0 + bv0)
    k_gemm<128, 1, 2><<<gblk, 256>>>(bufB, Wv, bv, bufA, n, 1, mask);
    //                 h = relu(z @ Wo0 + bo0)
    k_gemm<128, 0, 1><<<gblk, 256>>>(bufA, Wo, bo, bufB, n, 0, mask);

    // attn layer 1 (collapsed): z = mask * (h @ Wv1 + bv1)
    k_gemm<128, 0, 2><<<gblk, 256>>>(bufB, Wv + HID * HID, bv + HID, bufA, n, 0, mask);
    //                 out = relu(z @ Wo1 + bo1)
    k_gemm<128, 0, 1><<<gblk, 256>>>(bufA, Wo + HID * HID, bo + HID, out, n, 0, mask);
}

// round 7
// speedup vs baseline: 1.6230x; 1.6230x over previous
#include <cuda_runtime.h>
#include <cuda_bf16.h>
#include <cstdint>

#define NMAX 50000
#define HID 128

// ---------------- scratch ----------------
__device__ float g_bufA[NMAX * HID];
__device__ float g_bufB[NMAX * HID];
__device__ float g_mask[NMAX];
__device__ float g_colsum[HID];
__device__ float g_colsq[HID];
__device__ float g_bnscale[2][HID];
__device__ float g_bnshift[2][HID];
// transposed+split weights ([n][k] bf16): W1T(128x256) then 5x(128x128), hi/lo
__device__ __nv_bfloat16 g_BtH[32768 + 5 * 16384];
__device__ __nv_bfloat16 g_BtL[32768 + 5 * 16384];

// ---------------- helpers ----------------
__device__ __forceinline__ uint32_t smem_u32(const void* p) {
    uint32_t a;
    asm("{ .reg .u64 t; cvta.to.shared.u64 t, %1; cvt.u32.u64 %0, t; }"
        : "=r"(a) : "l"(p));
    return a;
}
__device__ __forceinline__ void ldsm4(uint32_t* r, uint32_t addr) {
    asm volatile("ldmatrix.sync.aligned.m8n8.x4.shared.b16 {%0,%1,%2,%3}, [%4];"
                 : "=r"(r[0]), "=r"(r[1]), "=r"(r[2]), "=r"(r[3]) : "r"(addr));
}
__device__ __forceinline__ void mma16816(float* c, const uint32_t* a, const uint32_t* b) {
    asm volatile(
        "mma.sync.aligned.m16n8k16.row.col.f32.bf16.bf16.f32 "
        "{%0,%1,%2,%3}, {%4,%5,%6,%7}, {%8,%9}, {%0,%1,%2,%3};"
        : "+f"(c[0]), "+f"(c[1]), "+f"(c[2]), "+f"(c[3])
        : "r"(a[0]), "r"(a[1]), "r"(a[2]), "r"(a[3]), "r"(b[0]), "r"(b[1]));
}
__device__ __forceinline__ uint32_t pack_bf2(__nv_bfloat16 a, __nv_bfloat16 b) {
    return ((uint32_t)__bfloat16_as_ushort(b) << 16) | (uint32_t)__bfloat16_as_ushort(a);
}
// XOR-swizzled offset inside a 128row x 128col bf16 tile (256B row stride)
__device__ __forceinline__ uint32_t swzb(int r, int kbyte) {
    return (uint32_t)r * 256u + (uint32_t)(kbyte ^ ((r & 7) << 4));
}

// ---------------- small kernels ----------------
__global__ void k_init(float* mask, int n) {
    int i = blockIdx.x * blockDim.x + threadIdx.x;
    if (i < n) mask[i] = 0.f;
    if (i < HID) { g_colsum[i] = 0.f; g_colsq[i] = 0.f; }
}
__global__ void k_scatter(const int* __restrict__ dst, int E, float* __restrict__ mask) {
    int e = blockIdx.x * blockDim.x + threadIdx.x;
    if (e < E) mask[dst[e]] = 1.0f;
}
__global__ void k_finalize(const float* __restrict__ g, const float* __restrict__ beta,
                           int idx, int n) {
    int c = threadIdx.x;
    float inv = 1.0f / (float)n;
    float mean = g_colsum[c] * inv;
    float var = g_colsq[c] * inv - mean * mean;
    float sc = g[c] * rsqrtf(var + 1e-5f);
    g_bnscale[idx][c] = sc;
    g_bnshift[idx][c] = beta[c] - sc * mean;
    g_colsum[c] = 0.f;
    g_colsq[c] = 0.f;
}
// transpose + hi/lo split weights into [n][k] bf16
__global__ void k_prep(const float* __restrict__ W1, const float* __restrict__ W2,
                       const float* __restrict__ Wv, const float* __restrict__ Wo) {
    int m = blockIdx.y;
    const float* src; int K, off;
    switch (m) {
        case 0: src = W1; K = 256; off = 0; break;
        case 1: src = W2; K = 128; off = 32768; break;
        case 2: src = Wv; K = 128; off = 49152; break;
        case 3: src = Wo; K = 128; off = 65536; break;
        case 4: src = Wv + 16384; K = 128; off = 81920; break;
        default: src = Wo + 16384; K = 128; off = 98304; break;
    }
    int idx = blockIdx.x * 256 + threadIdx.x;
    if (idx < K * 128) {
        int k = idx >> 7, nn = idx & 127;
        float v = src[idx];
        __nv_bfloat16 h = __float2bfloat16_rn(v);
        __nv_bfloat16 l = __float2bfloat16_rn(v - __bfloat162float(h));
        g_BtH[off + nn * K + k] = h;
        g_BtL[off + nn * K + k] = l;
    }
}

// ---------------- staging ----------------
// load 128 rows x 128 cols fp32 (optional BN+relu), split hi/lo, swizzled store
template <int PRO>
__device__ __forceinline__ void stage_act(const float* __restrict__ A, int Kld, int kcol0,
                                          int rowBase, int n, char* dH, char* dL,
                                          int bnIdx, int tid) {
#pragma unroll
    for (int it = 0; it < 16; it++) {
        int f4 = tid + 256 * it;
        int r = f4 >> 5;
        int kk = (f4 & 31) * 4;
        int row = rowBase + r;
        float4 v = make_float4(0.f, 0.f, 0.f, 0.f);
        if (row < n) v = *(const float4*)(A + (size_t)row * Kld + kcol0 + kk);
        if (PRO) {
            const float* sc = g_bnscale[bnIdx];
            const float* sh = g_bnshift[bnIdx];
            int gk = kcol0 + kk;
            v.x = fmaxf(fmaf(sc[gk + 0], v.x, sh[gk + 0]), 0.f);
            v.y = fmaxf(fmaf(sc[gk + 1], v.y, sh[gk + 1]), 0.f);
            v.z = fmaxf(fmaf(sc[gk + 2], v.z, sh[gk + 2]), 0.f);
            v.w = fmaxf(fmaf(sc[gk + 3], v.w, sh[gk + 3]), 0.f);
        }
        __nv_bfloat16 h0 = __float2bfloat16_rn(v.x), h1 = __float2bfloat16_rn(v.y);
        __nv_bfloat16 h2 = __float2bfloat16_rn(v.z), h3 = __float2bfloat16_rn(v.w);
        __nv_bfloat16 l0 = __float2bfloat16_rn(v.x - __bfloat162float(h0));
        __nv_bfloat16 l1 = __float2bfloat16_rn(v.y - __bfloat162float(h1));
        __nv_bfloat16 l2 = __float2bfloat16_rn(v.z - __bfloat162float(h2));
        __nv_bfloat16 l3 = __float2bfloat16_rn(v.w - __bfloat162float(h3));
        uint32_t so = swzb(r, kk * 2);
        *(uint2*)(dH + so) = make_uint2(pack_bf2(h0, h1), pack_bf2(h2, h3));
        *(uint2*)(dL + so) = make_uint2(pack_bf2(l0, l1), pack_bf2(l2, l3));
    }
}
// stage prepped bf16 weights (hi/lo) [128][Kw] chunk k0..k0+127 into swizzled smem
__device__ __forceinline__ void stage_w(const __nv_bfloat16* __restrict__ WH,
                                        const __nv_bfloat16* __restrict__ WL, int Kw,
                                        int k0, char* dH, char* dL, int tid) {
#pragma unroll
    for (int it = 0; it < 16; it++) {
        int idx = tid + 256 * it;
        int nr = idx >> 5;
        int kk = (idx & 31) * 4;
        uint2 h = *(const uint2*)(WH + (size_t)nr * Kw + k0 + kk);
        uint2 l = *(const uint2*)(WL + (size_t)nr * Kw + k0 + kk);
        uint32_t so = swzb(nr, kk * 2);
        *(uint2*)(dH + so) = h;
        *(uint2*)(dL + so) = l;
    }
}

// ---------------- core warp GEMM over one 128x128x128 tile (3-pass hi/lo) --------
__device__ __forceinline__ void gemm_tile(uint32_t sAH, uint32_t sAL, uint32_t sWH,
                                          uint32_t sWL, float acc[2][8][4], int wm,
                                          int wn, int lane) {
    const uint32_t aBase = (uint32_t)(wm * 32 + (lane & 15)) * 256u;
    const uint32_t aXor = (uint32_t)(((wm * 32 + (lane & 15)) & 7) << 4);
    const int aKb = (lane >> 4) * 16;  // byte offset within k-chunk
    const int nB = wn * 64 + (lane & 7) + ((lane & 16) ? 8 : 0);
    const uint32_t bBase = (uint32_t)nB * 256u;
    const uint32_t bXor = (uint32_t)((nB & 7) << 4);
    const int bKb = (lane & 8) ? 16 : 0;

#pragma unroll
    for (int ks = 0; ks < 8; ks++) {
        const int kb = ks * 32;
        uint32_t Ah[2][4], Al[2][4], Bh[4][4], Bl[4][4];
#pragma unroll
        for (int t = 0; t < 2; t++) {
            uint32_t off = aBase + (uint32_t)t * 4096u + (uint32_t)((kb + aKb) ^ (int)aXor);
            ldsm4(Ah[t], sAH + off);
            ldsm4(Al[t], sAL + off);
        }
#pragma unroll
        for (int g = 0; g < 4; g++) {
            uint32_t off = bBase + (uint32_t)g * 4096u + (uint32_t)((kb + bKb) ^ (int)bXor);
            ldsm4(Bh[g], sWH + off);
            ldsm4(Bl[g], sWL + off);
        }
#pragma unroll
        for (int t = 0; t < 2; t++)
#pragma unroll
            for (int nt = 0; nt < 8; nt++) {
                const uint32_t* bh = &Bh[nt >> 1][(nt & 1) * 2];
                const uint32_t* bl = &Bl[nt >> 1][(nt & 1) * 2];
                mma16816(acc[t][nt], Ah[t], bh);
                mma16816(acc[t][nt], Ah[t], bl);
                mma16816(acc[t][nt], Al[t], bh);
            }
    }
}

// ---------------- encoder GEMM kernel (fp32 out + fused BN stats) ----------------
// smem: actH(32K) actL(32K) wH(32K) wL(32K) ssum(512) ssq(512)
#define ENC_SMEM (4 * 32768 + 1024)
template <int KC, int PRO>
__global__ void __launch_bounds__(256, 1)
k_enc(const float* __restrict__ A, int btOff, const float* __restrict__ bias,
      float* __restrict__ out, int n, int bnIdx) {
    extern __shared__ char smem[];
    char* aH = smem;
    char* aL = smem + 32768;
    char* wH = smem + 65536;
    char* wL = smem + 98304;
    float* ssum = (float*)(smem + 131072);
    float* ssq = ssum + 128;
    const uint32_t sb = smem_u32(smem);
    const int tid = threadIdx.x, lane = tid & 31, wid = tid >> 5;
    const int wm = wid & 3, wn = wid >> 2;
    const int rowBase = blockIdx.x * 128;

    if (tid < 128) { ssum[tid] = 0.f; ssq[tid] = 0.f; }

    float acc[2][8][4];
#pragma unroll
    for (int t = 0; t < 2; t++)
#pragma unroll
        for (int nt = 0; nt < 8; nt++)
#pragma unroll
            for (int j = 0; j < 4; j++) acc[t][nt][j] = 0.f;

#pragma unroll
    for (int c = 0; c < KC; c++) {
        if (c) __syncthreads();
        stage_act<PRO>(A, KC * 128, c * 128, rowBase, n, aH, aL, bnIdx, tid);
        stage_w(g_BtH + btOff, g_BtL + btOff, KC * 128, c * 128, wH, wL, tid);
        __syncthreads();
        gemm_tile(sb, sb + 32768, sb + 65536, sb + 98304, acc, wm, wn, lane);
    }
    __syncthreads();

    // epilogue: bias, store fp32, fused column stats
    const int r0 = rowBase + wm * 32 + (lane >> 2);
    const int colb = wn * 64 + (lane & 3) * 2;
#pragma unroll
    for (int nt = 0; nt < 8; nt++) {
        int cc = colb + nt * 8;
        float bx = bias[cc], by = bias[cc + 1];
        float p0 = 0.f, p1 = 0.f, q0 = 0.f, q1 = 0.f;
#pragma unroll
        for (int t = 0; t < 2; t++) {
#pragma unroll
            for (int h = 0; h < 2; h++) {
                int row = r0 + t * 16 + h * 8;
                float y0 = acc[t][nt][h * 2] + bx;
                float y1 = acc[t][nt][h * 2 + 1] + by;
                if (row < n) {
                    *(float2*)(out + (size_t)row * HID + cc) = make_float2(y0, y1);
                    p0 += y0; q0 += y0 * y0;
                    p1 += y1; q1 += y1 * y1;
                }
            }
        }
#pragma unroll
        for (int m = 4; m <= 16; m <<= 1) {
            p0 += __shfl_xor_sync(~0u, p0, m);
            p1 += __shfl_xor_sync(~0u, p1, m);
            q0 += __shfl_xor_sync(~0u, q0, m);
            q1 += __shfl_xor_sync(~0u, q1, m);
        }
        if ((lane >> 2) == 0) {
            atomicAdd(&ssum[cc], p0);
            atomicAdd(&ssum[cc + 1], p1);
            atomicAdd(&ssq[cc], q0);
            atomicAdd(&ssq[cc + 1], q1);
        }
    }
    __syncthreads();
    if (tid < 128) {
        atomicAdd(&g_colsum[tid], ssum[tid]);
        atomicAdd(&g_colsq[tid], ssq[tid]);
    }
}

// ---------------- fused 4-GEMM attention kernel ----------------
// smem: act0H act0L act1H act1L wH wL  (6 x 32KB = 192KB)
#define FUS_SMEM (6 * 32768)
__global__ void __launch_bounds__(256, 1)
k_fused(const float* __restrict__ A, const float* __restrict__ bv,
        const float* __restrict__ bo, float* __restrict__ out, int n) {
    extern __shared__ char smem[];
    const uint32_t sb = smem_u32(smem);
    const int tid = threadIdx.x, lane = tid & 31, wid = tid >> 5;
    const int wm = wid & 3, wn = wid >> 2;
    const int rowBase = blockIdx.x * 128;

    const int woffs[4] = {49152, 65536, 81920, 98304};
    const float* biases[4] = {bv, bo, bv + HID, bo + HID};

    // initial: load y2 with BN#1 + relu into act buffer 0
    stage_act<1>(A, 128, 0, rowBase, n, smem, smem + 32768, 1, tid);

    int p = 0;
    for (int s = 0; s < 4; s++) {
        __syncthreads();
        stage_w(g_BtH + woffs[s], g_BtL + woffs[s], 128, 0, smem + 131072,
                smem + 163840, tid);
        __syncthreads();

        float acc[2][8][4];
#pragma unroll
        for (int t = 0; t < 2; t++)
#pragma unroll
            for (int nt = 0; nt < 8; nt++)
#pragma unroll
                for (int j = 0; j < 4; j++) acc[t][nt][j] = 0.f;

        uint32_t sA = sb + (uint32_t)p * 65536u;
        gemm_tile(sA, sA + 32768, sb + 131072, sb + 163840, acc, wm, wn, lane);

        const float* bias = biases[s];
        const bool isMask = (s & 1) == 0;
        const bool last = (s == 3);
        char* dH = smem + (p ^ 1) * 65536;
        char* dL = dH + 32768;

        float mk[2][2];
        if (isMask) {
#pragma unroll
            for (int t = 0; t < 2; t++)
#pragma unroll
                for (int h = 0; h < 2; h++) {
                    int row = rowBase + wm * 32 + t * 16 + h * 8 + (lane >> 2);
                    mk[t][h] = (row < n) ? g_mask[row] : 0.f;
                }
        }
        const int colb = wn * 64 + (lane & 3) * 2;
#pragma unroll
        for (int nt = 0; nt < 8; nt++) {
            int cc = colb + nt * 8;
            float bx = bias[cc], by = bias[cc + 1];
#pragma unroll
            for (int t = 0; t < 2; t++) {
#pragma unroll
                for (int h = 0; h < 2; h++) {
                    float y0 = acc[t][nt][h * 2] + bx;
                    float y1 = acc[t][nt][h * 2 + 1] + by;
                    if (isMask) {
                        y0 *= mk[t][h];
                        y1 *= mk[t][h];
                    } else {
                        y0 = fmaxf(y0, 0.f);
                        y1 = fmaxf(y1, 0.f);
                    }
                    int rl = wm * 32 + t * 16 + h * 8 + (lane >> 2);
                    if (last) {
                        int row = rowBase + rl;
                        if (row < n)
                            *(float2*)(out + (size_t)row * HID + cc) = make_float2(y0, y1);
                    } else {
                        __nv_bfloat16 h0 = __float2bfloat16_rn(y0);
                        __nv_bfloat16 h1 = __float2bfloat16_rn(y1);
                        uint32_t hi = pack_bf2(h0, h1);
                        uint32_t lo = pack_bf2(
                            __float2bfloat16_rn(y0 - __bfloat162float(h0)),
                            __float2bfloat16_rn(y1 - __bfloat162float(h1)));
                        uint32_t so = swzb(rl, cc * 2);
                        *(uint32_t*)(dH + so) = hi;
                        *(uint32_t*)(dL + so) = lo;
                    }
                }
            }
        }
        p ^= 1;
    }
}

// ---------------- launch ----------------
extern "C" void kernel_launch(void* const* d_in, const int* in_sizes, int n_in,
                              void* d_out, int out_size) {
    const float* x   = (const float*)d_in[0];
    const int*   ei  = (const int*)d_in[1];
    const float* W1  = (const float*)d_in[2];
    const float* b1  = (const float*)d_in[3];
    const float* g1  = (const float*)d_in[4];
    const float* be1 = (const float*)d_in[5];
    const float* W2  = (const float*)d_in[6];
    const float* b2  = (const float*)d_in[7];
    const float* g2  = (const float*)d_in[8];
    const float* be2 = (const float*)d_in[9];
    // d_in[10..13] = Wq,bq,Wk,bk : mathematically unused (softmax over dst sums to 1)
    const float* Wv  = (const float*)d_in[14];
    const float* bv  = (const float*)d_in[15];
    const float* Wo  = (const float*)d_in[16];
    const float* bo  = (const float*)d_in[17];
    float* out = (float*)d_out;

    const int n = in_sizes[0] / 256;
    const int E = in_sizes[1] / 2;
    const int* dst = ei + E;

    float *bufA, *bufB, *mask;
    cudaGetSymbolAddress((void**)&bufA, g_bufA);
    cudaGetSymbolAddress((void**)&bufB, g_bufB);
    cudaGetSymbolAddress((void**)&mask, g_mask);

    cudaFuncSetAttribute(k_enc<2, 0>, cudaFuncAttributeMaxDynamicSharedMemorySize, ENC_SMEM);
    cudaFuncSetAttribute(k_enc<1, 1>, cudaFuncAttributeMaxDynamicSharedMemorySize, ENC_SMEM);
    cudaFuncSetAttribute(k_fused, cudaFuncAttributeMaxDynamicSharedMemorySize, FUS_SMEM);

    const int gblk = (n + 127) / 128;

    k_prep<<<dim3(128, 6), 256>>>(W1, W2, Wv, Wo);
    k_init<<<(n + 255) / 256, 256>>>(mask, n);
    k_scatter<<<(E + 255) / 256, 256>>>(dst, E, mask);

    // encoder layer 1: y1 = x @ W1 + b1 (stats fused) -> BN #0
    k_enc<2, 0><<<gblk, 256, ENC_SMEM>>>(x, 0, b1, bufA, n, 0);
    k_finalize<<<1, 128>>>(g1, be1, 0, n);

    // encoder layer 2: y2 = relu(bn0(y1)) @ W2 + b2 (stats fused) -> BN #1
    k_enc<1, 1><<<gblk, 256, ENC_SMEM>>>(bufA, 32768, b2, bufB, n, 0);
    k_finalize<<<1, 128>>>(g2, be2, 1, n);

    // fused attention stack (Wv0/mask -> Wo0/relu -> Wv1/mask -> Wo1/relu)
    k_fused<<<gblk, 256, FUS_SMEM>>>(bufB, bv, bo, out, n);
}

// round 8
// speedup vs baseline: 1.8133x; 1.1173x over previous
#include <cuda_runtime.h>
#include <cuda_bf16.h>
#include <cstdint>

#define NMAX 50000
#define HID 128

// ---------------- scratch ----------------
__device__ float g_bufA[NMAX * HID];
__device__ float g_bufB[NMAX * HID];
__device__ float g_mask[NMAX];
__device__ float g_colsum[HID];
__device__ float g_colsq[HID];
__device__ float g_bnscale[2][HID];
__device__ float g_bnshift[2][HID];
// transposed+split weights ([n][k] bf16): W1T(128x256) then 5x(128x128), hi/lo
__device__ __nv_bfloat16 g_BtH[32768 + 5 * 16384];
__device__ __nv_bfloat16 g_BtL[32768 + 5 * 16384];

// ---------------- helpers ----------------
__device__ __forceinline__ uint32_t smem_u32(const void* p) {
    uint32_t a;
    asm("{ .reg .u64 t; cvta.to.shared.u64 t, %1; cvt.u32.u64 %0, t; }"
        : "=r"(a) : "l"(p));
    return a;
}
__device__ __forceinline__ void ldsm4(uint32_t* r, uint32_t addr) {
    asm volatile("ldmatrix.sync.aligned.m8n8.x4.shared.b16 {%0,%1,%2,%3}, [%4];"
                 : "=r"(r[0]), "=r"(r[1]), "=r"(r[2]), "=r"(r[3]) : "r"(addr));
}
__device__ __forceinline__ void mma16816(float* c, const uint32_t* a, const uint32_t* b) {
    asm volatile(
        "mma.sync.aligned.m16n8k16.row.col.f32.bf16.bf16.f32 "
        "{%0,%1,%2,%3}, {%4,%5,%6,%7}, {%8,%9}, {%0,%1,%2,%3};"
        : "+f"(c[0]), "+f"(c[1]), "+f"(c[2]), "+f"(c[3])
        : "r"(a[0]), "r"(a[1]), "r"(a[2]), "r"(a[3]), "r"(b[0]), "r"(b[1]));
}
__device__ __forceinline__ uint32_t pack_bf2(__nv_bfloat16 a, __nv_bfloat16 b) {
    return ((uint32_t)__bfloat16_as_ushort(b) << 16) | (uint32_t)__bfloat16_as_ushort(a);
}
// XOR-swizzled offset inside a 128row x 128col bf16 tile (256B row stride)
__device__ __forceinline__ uint32_t swzb(int r, int kbyte) {
    return (uint32_t)r * 256u + (uint32_t)(kbyte ^ ((r & 7) << 4));
}

// ---------------- small kernels ----------------
__global__ void k_init(float* mask, int n) {
    int i = blockIdx.x * blockDim.x + threadIdx.x;
    if (i < n) mask[i] = 0.f;
    if (i < HID) { g_colsum[i] = 0.f; g_colsq[i] = 0.f; }
}
__global__ void k_scatter(const int* __restrict__ dst, int E, float* __restrict__ mask) {
    int e = blockIdx.x * blockDim.x + threadIdx.x;
    if (e < E) mask[dst[e]] = 1.0f;
}
__global__ void k_finalize(const float* __restrict__ g, const float* __restrict__ beta,
                           int idx, int n) {
    int c = threadIdx.x;
    float inv = 1.0f / (float)n;
    float mean = g_colsum[c] * inv;
    float var = g_colsq[c] * inv - mean * mean;
    float sc = g[c] * rsqrtf(var + 1e-5f);
    g_bnscale[idx][c] = sc;
    g_bnshift[idx][c] = beta[c] - sc * mean;
    g_colsum[c] = 0.f;
    g_colsq[c] = 0.f;
}
// transpose + hi/lo split weights into [n][k] bf16
__global__ void k_prep(const float* __restrict__ W1, const float* __restrict__ W2,
                       const float* __restrict__ Wv, const float* __restrict__ Wo) {
    int m = blockIdx.y;
    const float* src; int K, off;
    switch (m) {
        case 0: src = W1; K = 256; off = 0; break;
        case 1: src = W2; K = 128; off = 32768; break;
        case 2: src = Wv; K = 128; off = 49152; break;
        case 3: src = Wo; K = 128; off = 65536; break;
        case 4: src = Wv + 16384; K = 128; off = 81920; break;
        default: src = Wo + 16384; K = 128; off = 98304; break;
    }
    int idx = blockIdx.x * 256 + threadIdx.x;
    if (idx < K * 128) {
        int k = idx >> 7, nn = idx & 127;
        float v = src[idx];
        __nv_bfloat16 h = __float2bfloat16_rn(v);
        __nv_bfloat16 l = __float2bfloat16_rn(v - __bfloat162float(h));
        g_BtH[off + nn * K + k] = h;
        g_BtL[off + nn * K + k] = l;
    }
}

// ---------------- staging (512 threads) ----------------
template <int PRO>
__device__ __forceinline__ void stage_act(const float* __restrict__ A, int Kld, int kcol0,
                                          int rowBase, int n, char* dH, char* dL,
                                          int bnIdx, int tid) {
#pragma unroll
    for (int it = 0; it < 8; it++) {
        int f4 = tid + 512 * it;
        int r = f4 >> 5;
        int kk = (f4 & 31) * 4;
        int row = rowBase + r;
        float4 v = make_float4(0.f, 0.f, 0.f, 0.f);
        if (row < n) v = *(const float4*)(A + (size_t)row * Kld + kcol0 + kk);
        if (PRO) {
            const float* sc = g_bnscale[bnIdx];
            const float* sh = g_bnshift[bnIdx];
            int gk = kcol0 + kk;
            v.x = fmaxf(fmaf(sc[gk + 0], v.x, sh[gk + 0]), 0.f);
            v.y = fmaxf(fmaf(sc[gk + 1], v.y, sh[gk + 1]), 0.f);
            v.z = fmaxf(fmaf(sc[gk + 2], v.z, sh[gk + 2]), 0.f);
            v.w = fmaxf(fmaf(sc[gk + 3], v.w, sh[gk + 3]), 0.f);
        }
        __nv_bfloat16 h0 = __float2bfloat16_rn(v.x), h1 = __float2bfloat16_rn(v.y);
        __nv_bfloat16 h2 = __float2bfloat16_rn(v.z), h3 = __float2bfloat16_rn(v.w);
        __nv_bfloat16 l0 = __float2bfloat16_rn(v.x - __bfloat162float(h0));
        __nv_bfloat16 l1 = __float2bfloat16_rn(v.y - __bfloat162float(h1));
        __nv_bfloat16 l2 = __float2bfloat16_rn(v.z - __bfloat162float(h2));
        __nv_bfloat16 l3 = __float2bfloat16_rn(v.w - __bfloat162float(h3));
        uint32_t so = swzb(r, kk * 2);
        *(uint2*)(dH + so) = make_uint2(pack_bf2(h0, h1), pack_bf2(h2, h3));
        *(uint2*)(dL + so) = make_uint2(pack_bf2(l0, l1), pack_bf2(l2, l3));
    }
}
__device__ __forceinline__ void stage_w(const __nv_bfloat16* __restrict__ WH,
                                        const __nv_bfloat16* __restrict__ WL, int Kw,
                                        int k0, char* dH, char* dL, int tid) {
#pragma unroll
    for (int it = 0; it < 8; it++) {
        int idx = tid + 512 * it;
        int nr = idx >> 5;
        int kk = (idx & 31) * 4;
        uint2 h = *(const uint2*)(WH + (size_t)nr * Kw + k0 + kk);
        uint2 l = *(const uint2*)(WL + (size_t)nr * Kw + k0 + kk);
        uint32_t so = swzb(nr, kk * 2);
        *(uint2*)(dH + so) = h;
        *(uint2*)(dL + so) = l;
    }
}

// ---------------- warp GEMM: 32x32 output per warp, 4x4 warp grid, 3-pass hi/lo ----
__device__ __forceinline__ void gemm_tile(uint32_t sAH, uint32_t sAL, uint32_t sWH,
                                          uint32_t sWL, float acc[2][4][4], int wm,
                                          int wn, int lane) {
    const uint32_t aBase = (uint32_t)(wm * 32 + (lane & 15)) * 256u;
    const uint32_t aXor = (uint32_t)(((wm * 32 + (lane & 15)) & 7) << 4);
    const int aKb = (lane >> 4) * 16;
    const int nB = wn * 32 + (lane & 7) + ((lane & 16) ? 8 : 0);
    const uint32_t bBase = (uint32_t)nB * 256u;
    const uint32_t bXor = (uint32_t)((nB & 7) << 4);
    const int bKb = (lane & 8) ? 16 : 0;

#pragma unroll
    for (int ks = 0; ks < 8; ks++) {
        const int kb = ks * 32;
        uint32_t Ah[2][4], Al[2][4], Bh[2][4], Bl[2][4];
#pragma unroll
        for (int t = 0; t < 2; t++) {
            uint32_t off = aBase + (uint32_t)t * 4096u + (uint32_t)((kb + aKb) ^ (int)aXor);
            ldsm4(Ah[t], sAH + off);
            ldsm4(Al[t], sAL + off);
        }
#pragma unroll
        for (int g = 0; g < 2; g++) {
            uint32_t off = bBase + (uint32_t)g * 4096u + (uint32_t)((kb + bKb) ^ (int)bXor);
            ldsm4(Bh[g], sWH + off);
            ldsm4(Bl[g], sWL + off);
        }
#pragma unroll
        for (int t = 0; t < 2; t++)
#pragma unroll
            for (int nt = 0; nt < 4; nt++) {
                const uint32_t* bh = &Bh[nt >> 1][(nt & 1) * 2];
                const uint32_t* bl = &Bl[nt >> 1][(nt & 1) * 2];
                mma16816(acc[t][nt], Ah[t], bh);
                mma16816(acc[t][nt], Ah[t], bl);
                mma16816(acc[t][nt], Al[t], bh);
            }
    }
}

// ---------------- encoder GEMM kernel (fp32 out + fused BN stats) ----------------
#define ENC_SMEM (4 * 32768 + 1024)
template <int KC, int PRO>
__global__ void __launch_bounds__(512, 1)
k_enc(const float* __restrict__ A, int btOff, const float* __restrict__ bias,
      float* __restrict__ out, int n, int bnIdx) {
    extern __shared__ char smem[];
    char* aH = smem;
    char* aL = smem + 32768;
    char* wH = smem + 65536;
    char* wL = smem + 98304;
    float* ssum = (float*)(smem + 131072);
    float* ssq = ssum + 128;
    const uint32_t sb = smem_u32(smem);
    const int tid = threadIdx.x, lane = tid & 31, wid = tid >> 5;
    const int wm = wid & 3, wn = wid >> 2;
    const int rowBase = blockIdx.x * 128;

    if (tid < 128) { ssum[tid] = 0.f; ssq[tid] = 0.f; }

    float acc[2][4][4];
#pragma unroll
    for (int t = 0; t < 2; t++)
#pragma unroll
        for (int nt = 0; nt < 4; nt++)
#pragma unroll
            for (int j = 0; j < 4; j++) acc[t][nt][j] = 0.f;

#pragma unroll
    for (int c = 0; c < KC; c++) {
        if (c) __syncthreads();
        stage_act<PRO>(A, KC * 128, c * 128, rowBase, n, aH, aL, bnIdx, tid);
        stage_w(g_BtH + btOff, g_BtL + btOff, KC * 128, c * 128, wH, wL, tid);
        __syncthreads();
        gemm_tile(sb, sb + 32768, sb + 65536, sb + 98304, acc, wm, wn, lane);
    }
    __syncthreads();

    // epilogue: bias, store fp32, fused column stats
    const int r0 = rowBase + wm * 32 + (lane >> 2);
    const int colb = wn * 32 + (lane & 3) * 2;
#pragma unroll
    for (int nt = 0; nt < 4; nt++) {
        int cc = colb + nt * 8;
        float bx = bias[cc], by = bias[cc + 1];
        float p0 = 0.f, p1 = 0.f, q0 = 0.f, q1 = 0.f;
#pragma unroll
        for (int t = 0; t < 2; t++) {
#pragma unroll
            for (int h = 0; h < 2; h++) {
                int row = r0 + t * 16 + h * 8;
                float y0 = acc[t][nt][h * 2] + bx;
                float y1 = acc[t][nt][h * 2 + 1] + by;
                if (row < n) {
                    *(float2*)(out + (size_t)row * HID + cc) = make_float2(y0, y1);
                    p0 += y0; q0 += y0 * y0;
                    p1 += y1; q1 += y1 * y1;
                }
            }
        }
#pragma unroll
        for (int m = 4; m <= 16; m <<= 1) {
            p0 += __shfl_xor_sync(~0u, p0, m);
            p1 += __shfl_xor_sync(~0u, p1, m);
            q0 += __shfl_xor_sync(~0u, q0, m);
            q1 += __shfl_xor_sync(~0u, q1, m);
        }
        if ((lane >> 2) == 0) {
            atomicAdd(&ssum[cc], p0);
            atomicAdd(&ssum[cc + 1], p1);
            atomicAdd(&ssq[cc], q0);
            atomicAdd(&ssq[cc + 1], q1);
        }
    }
    __syncthreads();
    if (tid < 128) {
        atomicAdd(&g_colsum[tid], ssum[tid]);
        atomicAdd(&g_colsq[tid], ssq[tid]);
    }
}

// ---------------- fused 4-GEMM attention kernel ----------------
// smem: act0H act0L act1H act1L wH wL  (6 x 32KB = 192KB)
#define FUS_SMEM (6 * 32768)
__global__ void __launch_bounds__(512, 1)
k_fused(const float* __restrict__ A, const float* __restrict__ bv,
        const float* __restrict__ bo, float* __restrict__ out, int n) {
    extern __shared__ char smem[];
    const uint32_t sb = smem_u32(smem);
    const int tid = threadIdx.x, lane = tid & 31, wid = tid >> 5;
    const int wm = wid & 3, wn = wid >> 2;
    const int rowBase = blockIdx.x * 128;

    const int woffs[4] = {49152, 65536, 81920, 98304};
    const float* biases[4] = {bv, bo, bv + HID, bo + HID};

    // initial: load y2 with BN#1 + relu into act buffer 0
    stage_act<1>(A, 128, 0, rowBase, n, smem, smem + 32768, 1, tid);

    int p = 0;
    for (int s = 0; s < 4; s++) {
        __syncthreads();
        stage_w(g_BtH + woffs[s], g_BtL + woffs[s], 128, 0, smem + 131072,
                smem + 163840, tid);
        __syncthreads();

        float acc[2][4][4];
#pragma unroll
        for (int t = 0; t < 2; t++)
#pragma unroll
            for (int nt = 0; nt < 4; nt++)
#pragma unroll
                for (int j = 0; j < 4; j++) acc[t][nt][j] = 0.f;

        uint32_t sA = sb + (uint32_t)p * 65536u;
        gemm_tile(sA, sA + 32768, sb + 131072, sb + 163840, acc, wm, wn, lane);

        const float* bias = biases[s];
        const bool isMask = (s & 1) == 0;
        const bool last = (s == 3);
        char* dH = smem + (p ^ 1) * 65536;
        char* dL = dH + 32768;

        float mk[2][2];
        if (isMask) {
#pragma unroll
            for (int t = 0; t < 2; t++)
#pragma unroll
                for (int h = 0; h < 2; h++) {
                    int row = rowBase + wm * 32 + t * 16 + h * 8 + (lane >> 2);
                    mk[t][h] = (row < n) ? g_mask[row] : 0.f;
                }
        }
        const int colb = wn * 32 + (lane & 3) * 2;
#pragma unroll
        for (int nt = 0; nt < 4; nt++) {
            int cc = colb + nt * 8;
            float bx = bias[cc], by = bias[cc + 1];
#pragma unroll
            for (int t = 0; t < 2; t++) {
#pragma unroll
                for (int h = 0; h < 2; h++) {
                    float y0 = acc[t][nt][h * 2] + bx;
                    float y1 = acc[t][nt][h * 2 + 1] + by;
                    if (isMask) {
                        y0 *= mk[t][h];
                        y1 *= mk[t][h];
                    } else {
                        y0 = fmaxf(y0, 0.f);
                        y1 = fmaxf(y1, 0.f);
                    }
                    int rl = wm * 32 + t * 16 + h * 8 + (lane >> 2);
                    if (last) {
                        int row = rowBase + rl;
                        if (row < n)
                            *(float2*)(out + (size_t)row * HID + cc) = make_float2(y0, y1);
                    } else {
                        __nv_bfloat16 h0 = __float2bfloat16_rn(y0);
                        __nv_bfloat16 h1 = __float2bfloat16_rn(y1);
                        uint32_t hi = pack_bf2(h0, h1);
                        uint32_t lo = pack_bf2(
                            __float2bfloat16_rn(y0 - __bfloat162float(h0)),
                            __float2bfloat16_rn(y1 - __bfloat162float(h1)));
                        uint32_t so = swzb(rl, cc * 2);
                        *(uint32_t*)(dH + so) = hi;
                        *(uint32_t*)(dL + so) = lo;
                    }
                }
            }
        }
        p ^= 1;
    }
}

// ---------------- launch ----------------
extern "C" void kernel_launch(void* const* d_in, const int* in_sizes, int n_in,
                              void* d_out, int out_size) {
    const float* x   = (const float*)d_in[0];
    const int*   ei  = (const int*)d_in[1];
    const float* W1  = (const float*)d_in[2];
    const float* b1  = (const float*)d_in[3];
    const float* g1  = (const float*)d_in[4];
    const float* be1 = (const float*)d_in[5];
    const float* W2  = (const float*)d_in[6];
    const float* b2  = (const float*)d_in[7];
    const float* g2  = (const float*)d_in[8];
    const float* be2 = (const float*)d_in[9];
    // d_in[10..13] = Wq,bq,Wk,bk : mathematically unused (softmax over dst sums to 1)
    const float* Wv  = (const float*)d_in[14];
    const float* bv  = (const float*)d_in[15];
    const float* Wo  = (const float*)d_in[16];
    const float* bo  = (const float*)d_in[17];
    float* out = (float*)d_out;

    const int n = in_sizes[0] / 256;
    const int E = in_sizes[1] / 2;
    const int* dst = ei + E;

    float *bufA, *bufB, *mask;
    cudaGetSymbolAddress((void**)&bufA, g_bufA);
    cudaGetSymbolAddress((void**)&bufB, g_bufB);
    cudaGetSymbolAddress((void**)&mask, g_mask);

    cudaFuncSetAttribute(k_enc<2, 0>, cudaFuncAttributeMaxDynamicSharedMemorySize, ENC_SMEM);
    cudaFuncSetAttribute(k_enc<1, 1>, cudaFuncAttributeMaxDynamicSharedMemorySize, ENC_SMEM);
    cudaFuncSetAttribute(k_fused, cudaFuncAttributeMaxDynamicSharedMemorySize, FUS_SMEM);

    const int gblk = (n + 127) / 128;

    k_prep<<<dim3(128, 6), 256>>>(W1, W2, Wv, Wo);
    k_init<<<(n + 255) / 256, 256>>>(mask, n);
    k_scatter<<<(E + 255) / 256, 256>>>(dst, E, mask);

    // encoder layer 1: y1 = x @ W1 + b1 (stats fused) -> BN #0
    k_enc<2, 0><<<gblk, 512, ENC_SMEM>>>(x, 0, b1, bufA, n, 0);
    k_finalize<<<1, 128>>>(g1, be1, 0, n);

    // encoder layer 2: y2 = relu(bn0(y1)) @ W2 + b2 (stats fused) -> BN #1
    k_enc<1, 1><<<gblk, 512, ENC_SMEM>>>(bufA, 32768, b2, bufB, n, 0);
    k_finalize<<<1, 128>>>(g2, be2, 1, n);

    // fused attention stack (Wv0/mask -> Wo0/relu -> Wv1/mask -> Wo1/relu)
    k_fused<<<gblk, 512, FUS_SMEM>>>(bufB, bv, bo, out, n);
}

// round 9
// speedup vs baseline: 1.8998x; 1.0477x over previous
#include <cuda_runtime.h>
#include <cuda_bf16.h>
#include <cstdint>

#define NMAX 50000
#define HID 128

// ---------------- scratch ----------------
__device__ __align__(16) float g_bufA[NMAX * HID];
__device__ __align__(16) float g_bufB[NMAX * HID];
__device__ float g_mask[NMAX];
__device__ float g_colsum[HID];
__device__ float g_colsq[HID];
__device__ float g_bnscale[2][HID];
__device__ float g_bnshift[2][HID];
// transposed+split weights ([n][k] bf16): W1T(128x256) then 5x(128x128), hi/lo
__device__ __align__(16) __nv_bfloat16 g_BtH[32768 + 5 * 16384];
__device__ __align__(16) __nv_bfloat16 g_BtL[32768 + 5 * 16384];

// ---------------- helpers ----------------
__device__ __forceinline__ uint32_t smem_u32(const void* p) {
    uint32_t a;
    asm("{ .reg .u64 t; cvta.to.shared.u64 t, %1; cvt.u32.u64 %0, t; }"
        : "=r"(a) : "l"(p));
    return a;
}
__device__ __forceinline__ void ldsm4(uint32_t* r, uint32_t addr) {
    asm volatile("ldmatrix.sync.aligned.m8n8.x4.shared.b16 {%0,%1,%2,%3}, [%4];"
                 : "=r"(r[0]), "=r"(r[1]), "=r"(r[2]), "=r"(r[3]) : "r"(addr));
}
__device__ __forceinline__ void mma16816(float* c, const uint32_t* a, const uint32_t* b) {
    asm volatile(
        "mma.sync.aligned.m16n8k16.row.col.f32.bf16.bf16.f32 "
        "{%0,%1,%2,%3}, {%4,%5,%6,%7}, {%8,%9}, {%0,%1,%2,%3};"
        : "+f"(c[0]), "+f"(c[1]), "+f"(c[2]), "+f"(c[3])
        : "r"(a[0]), "r"(a[1]), "r"(a[2]), "r"(a[3]), "r"(b[0]), "r"(b[1]));
}
__device__ __forceinline__ void cpasync16(uint32_t dst, const void* src) {
    asm volatile("cp.async.cg.shared.global [%0], [%1], 16;" :: "r"(dst), "l"(src));
}
#define CP_COMMIT() asm volatile("cp.async.commit_group;" ::: "memory")
#define CP_WAIT0() asm volatile("cp.async.wait_group 0;" ::: "memory")

__device__ __forceinline__ uint32_t pack_bf2(__nv_bfloat16 a, __nv_bfloat16 b) {
    return ((uint32_t)__bfloat16_as_ushort(b) << 16) | (uint32_t)__bfloat16_as_ushort(a);
}
// XOR-swizzled offset inside a 128row x 128col bf16 tile (256B row stride)
__device__ __forceinline__ uint32_t swzb(int r, int kbyte) {
    return (uint32_t)r * 256u + (uint32_t)(kbyte ^ ((r & 7) << 4));
}

// ---------------- small kernels ----------------
__global__ void k_init(float* mask, int n) {
    int i = blockIdx.x * blockDim.x + threadIdx.x;
    if (i < n) mask[i] = 0.f;
    if (i < HID) { g_colsum[i] = 0.f; g_colsq[i] = 0.f; }
}
__global__ void k_scatter(const int* __restrict__ dst, int E, float* __restrict__ mask) {
    int e = blockIdx.x * blockDim.x + threadIdx.x;
    if (e < E) mask[dst[e]] = 1.0f;
}
__global__ void k_finalize(const float* __restrict__ g, const float* __restrict__ beta,
                           int idx, int n) {
    int c = threadIdx.x;
    float inv = 1.0f / (float)n;
    float mean = g_colsum[c] * inv;
    float var = g_colsq[c] * inv - mean * mean;
    float sc = g[c] * rsqrtf(var + 1e-5f);
    g_bnscale[idx][c] = sc;
    g_bnshift[idx][c] = beta[c] - sc * mean;
    g_colsum[c] = 0.f;
    g_colsq[c] = 0.f;
}
// transpose + hi/lo split weights into [n][k] bf16
__global__ void k_prep(const float* __restrict__ W1, const float* __restrict__ W2,
                       const float* __restrict__ Wv, const float* __restrict__ Wo) {
    int m = blockIdx.y;
    const float* src; int K, off;
    switch (m) {
        case 0: src = W1; K = 256; off = 0; break;
        case 1: src = W2; K = 128; off = 32768; break;
        case 2: src = Wv; K = 128; off = 49152; break;
        case 3: src = Wo; K = 128; off = 65536; break;
        case 4: src = Wv + 16384; K = 128; off = 81920; break;
        default: src = Wo + 16384; K = 128; off = 98304; break;
    }
    int idx = blockIdx.x * 256 + threadIdx.x;
    if (idx < K * 128) {
        int k = idx >> 7, nn = idx & 127;
        float v = src[idx];
        __nv_bfloat16 h = __float2bfloat16_rn(v);
        __nv_bfloat16 l = __float2bfloat16_rn(v - __bfloat162float(h));
        g_BtH[off + nn * K + k] = h;
        g_BtL[off + nn * K + k] = l;
    }
}

// ---------------- staging ----------------
__device__ __forceinline__ void split_store(float4 v, int r, int kk, char* dH, char* dL) {
    __nv_bfloat16 h0 = __float2bfloat16_rn(v.x), h1 = __float2bfloat16_rn(v.y);
    __nv_bfloat16 h2 = __float2bfloat16_rn(v.z), h3 = __float2bfloat16_rn(v.w);
    __nv_bfloat16 l0 = __float2bfloat16_rn(v.x - __bfloat162float(h0));
    __nv_bfloat16 l1 = __float2bfloat16_rn(v.y - __bfloat162float(h1));
    __nv_bfloat16 l2 = __float2bfloat16_rn(v.z - __bfloat162float(h2));
    __nv_bfloat16 l3 = __float2bfloat16_rn(v.w - __bfloat162float(h3));
    uint32_t so = swzb(r, kk * 2);
    *(uint2*)(dH + so) = make_uint2(pack_bf2(h0, h1), pack_bf2(h2, h3));
    *(uint2*)(dL + so) = make_uint2(pack_bf2(l0, l1), pack_bf2(l2, l3));
}
template <int PRO>
__device__ __forceinline__ float4 bn_tf(float4 v, int gk, int bnIdx) {
    if (PRO) {
        const float* sc = g_bnscale[bnIdx];
        const float* sh = g_bnshift[bnIdx];
        v.x = fmaxf(fmaf(sc[gk + 0], v.x, sh[gk + 0]), 0.f);
        v.y = fmaxf(fmaf(sc[gk + 1], v.y, sh[gk + 1]), 0.f);
        v.z = fmaxf(fmaf(sc[gk + 2], v.z, sh[gk + 2]), 0.f);
        v.w = fmaxf(fmaf(sc[gk + 3], v.w, sh[gk + 3]), 0.f);
    }
    return v;
}
// direct stage: 128 rows x 128 cols fp32 -> bf16 hi/lo swizzled (512 threads)
template <int PRO>
__device__ __forceinline__ void stage_act(const float* __restrict__ A, int Kld, int kcol0,
                                          int rowBase, int n, char* dH, char* dL,
                                          int bnIdx, int tid) {
#pragma unroll
    for (int it = 0; it < 8; it++) {
        int f4 = tid + 512 * it;
        int r = f4 >> 5;
        int kk = (f4 & 31) * 4;
        int row = rowBase + r;
        float4 v = make_float4(0.f, 0.f, 0.f, 0.f);
        if (row < n) v = *(const float4*)(A + (size_t)row * Kld + kcol0 + kk);
        v = bn_tf<PRO>(v, kcol0 + kk, bnIdx);
        split_store(v, r, kk, dH, dL);
    }
}
// async weight stage: 128n x 128k chunk (256B rows) via cp.async, swizzled
__device__ __forceinline__ void stage_w_async(const __nv_bfloat16* __restrict__ WH,
                                              const __nv_bfloat16* __restrict__ WL,
                                              int Kw, int k0, uint32_t dH, uint32_t dL,
                                              int tid) {
#pragma unroll
    for (int it = 0; it < 4; it++) {
        int idx = tid + 512 * it;
        int nr = idx >> 4;
        int kg = (idx & 15) * 16;
        uint32_t so = swzb(nr, kg);
        const char* sh_ = (const char*)WH + (size_t)nr * Kw * 2 + k0 * 2 + kg;
        const char* sl_ = (const char*)WL + (size_t)nr * Kw * 2 + k0 * 2 + kg;
        cpasync16(dH + so, sh_);
        cpasync16(dL + so, sl_);
    }
}

// ---------------- warp GEMM: 32x32 per warp, 4x4 warp grid, 3-pass hi/lo ----------
__device__ __forceinline__ void gemm_tile(uint32_t sAH, uint32_t sAL, uint32_t sWH,
                                          uint32_t sWL, float acc[2][4][4], int wm,
                                          int wn, int lane) {
    const uint32_t aBase = (uint32_t)(wm * 32 + (lane & 15)) * 256u;
    const uint32_t aXor = (uint32_t)(((wm * 32 + (lane & 15)) & 7) << 4);
    const int aKb = (lane >> 4) * 16;
    const int nB = wn * 32 + (lane & 7) + ((lane & 16) ? 8 : 0);
    const uint32_t bBase = (uint32_t)nB * 256u;
    const uint32_t bXor = (uint32_t)((nB & 7) << 4);
    const int bKb = (lane & 8) ? 16 : 0;

#pragma unroll
    for (int ks = 0; ks < 8; ks++) {
        const int kb = ks * 32;
        uint32_t Ah[2][4], Al[2][4], Bh[2][4], Bl[2][4];
#pragma unroll
        for (int t = 0; t < 2; t++) {
            uint32_t off = aBase + (uint32_t)t * 4096u + (uint32_t)((kb + aKb) ^ (int)aXor);
            ldsm4(Ah[t], sAH + off);
            ldsm4(Al[t], sAL + off);
        }
#pragma unroll
        for (int g = 0; g < 2; g++) {
            uint32_t off = bBase + (uint32_t)g * 4096u + (uint32_t)((kb + bKb) ^ (int)bXor);
            ldsm4(Bh[g], sWH + off);
            ldsm4(Bl[g], sWL + off);
        }
        // pass-major: consecutive MMAs hit different accumulators
#pragma unroll
        for (int t = 0; t < 2; t++)
#pragma unroll
            for (int nt = 0; nt < 4; nt++)
                mma16816(acc[t][nt], Ah[t], &Bh[nt >> 1][(nt & 1) * 2]);
#pragma unroll
        for (int t = 0; t < 2; t++)
#pragma unroll
            for (int nt = 0; nt < 4; nt++)
                mma16816(acc[t][nt], Ah[t], &Bl[nt >> 1][(nt & 1) * 2]);
#pragma unroll
        for (int t = 0; t < 2; t++)
#pragma unroll
            for (int nt = 0; nt < 4; nt++)
                mma16816(acc[t][nt], Al[t], &Bh[nt >> 1][(nt & 1) * 2]);
    }
}

// ---------------- encoder GEMM kernel (fp32 out + fused BN stats) ----------------
// smem: actH actL | wH0 wL0 | wH1 wL1 | stats  (6*32KB + 1KB)
#define ENC_SMEM (6 * 32768 + 1024)
template <int KC, int PRO>
__global__ void __launch_bounds__(512, 1)
k_enc(const float* __restrict__ A, int btOff, const float* __restrict__ bias,
      float* __restrict__ out, int n, int bnIdx) {
    extern __shared__ char smem[];
    char* aH = smem;
    char* aL = smem + 32768;
    float* ssum = (float*)(smem + 196608);
    float* ssq = ssum + 128;
    const uint32_t sb = smem_u32(smem);
    const int tid = threadIdx.x, lane = tid & 31, wid = tid >> 5;
    const int wm = wid & 3, wn = wid >> 2;
    const int rowBase = blockIdx.x * 128;
    const int Kw = KC * 128;
    const __nv_bfloat16* WH = g_BtH + btOff;
    const __nv_bfloat16* WL = g_BtL + btOff;

    if (tid < 128) { ssum[tid] = 0.f; ssq[tid] = 0.f; }

    float acc[2][4][4];
#pragma unroll
    for (int t = 0; t < 2; t++)
#pragma unroll
        for (int nt = 0; nt < 4; nt++)
#pragma unroll
            for (int j = 0; j < 4; j++) acc[t][nt][j] = 0.f;

    // prefetch W chunk0 (async) + stage A chunk0 (direct)
    stage_w_async(WH, WL, Kw, 0, sb + 65536, sb + 98304, tid);
    CP_COMMIT();
    stage_act<PRO>(A, Kw, 0, rowBase, n, aH, aL, bnIdx, tid);
    CP_WAIT0();
    __syncthreads();

    if (KC == 2) {
        // prefetch A chunk1 into regs + W chunk1 async, under gemm of chunk0
        float4 areg[8];
#pragma unroll
        for (int it = 0; it < 8; it++) {
            int f4 = tid + 512 * it;
            int r = f4 >> 5;
            int kk = (f4 & 31) * 4;
            int row = rowBase + r;
            areg[it] = (row < n) ? *(const float4*)(A + (size_t)row * Kw + 128 + kk)
                                 : make_float4(0.f, 0.f, 0.f, 0.f);
        }
        stage_w_async(WH, WL, Kw, 128, sb + 131072, sb + 163840, tid);
        CP_COMMIT();
        gemm_tile(sb, sb + 32768, sb + 65536, sb + 98304, acc, wm, wn, lane);
        __syncthreads();
#pragma unroll
        for (int it = 0; it < 8; it++) {
            int f4 = tid + 512 * it;
            int r = f4 >> 5;
            int kk = (f4 & 31) * 4;
            split_store(bn_tf<PRO>(areg[it], 128 + kk, bnIdx), r, kk, aH, aL);
        }
        CP_WAIT0();
        __syncthreads();
        gemm_tile(sb, sb + 32768, sb + 131072, sb + 163840, acc, wm, wn, lane);
    } else {
        gemm_tile(sb, sb + 32768, sb + 65536, sb + 98304, acc, wm, wn, lane);
    }

    // epilogue: bias, store fp32, fused column stats
    const int r0 = rowBase + wm * 32 + (lane >> 2);
    const int colb = wn * 32 + (lane & 3) * 2;
#pragma unroll
    for (int nt = 0; nt < 4; nt++) {
        int cc = colb + nt * 8;
        float bx = bias[cc], by = bias[cc + 1];
        float p0 = 0.f, p1 = 0.f, q0 = 0.f, q1 = 0.f;
#pragma unroll
        for (int t = 0; t < 2; t++) {
#pragma unroll
            for (int h = 0; h < 2; h++) {
                int row = r0 + t * 16 + h * 8;
                float y0 = acc[t][nt][h * 2] + bx;
                float y1 = acc[t][nt][h * 2 + 1] + by;
                if (row < n) {
                    *(float2*)(out + (size_t)row * HID + cc) = make_float2(y0, y1);
                    p0 += y0; q0 += y0 * y0;
                    p1 += y1; q1 += y1 * y1;
                }
            }
        }
#pragma unroll
        for (int m = 4; m <= 16; m <<= 1) {
            p0 += __shfl_xor_sync(~0u, p0, m);
            p1 += __shfl_xor_sync(~0u, p1, m);
            q0 += __shfl_xor_sync(~0u, q0, m);
            q1 += __shfl_xor_sync(~0u, q1, m);
        }
        if ((lane >> 2) == 0) {
            atomicAdd(&ssum[cc], p0);
            atomicAdd(&ssum[cc + 1], p1);
            atomicAdd(&ssq[cc], q0);
            atomicAdd(&ssq[cc + 1], q1);
        }
    }
    __syncthreads();
    if (tid < 128) {
        atomicAdd(&g_colsum[tid], ssum[tid]);
        atomicAdd(&g_colsq[tid], ssq[tid]);
    }
}

// ---------------- fused 4-GEMM attention kernel ----------------
// smem: actH actL | wH0 wL0 | wH1 wL1  (6 x 32KB = 192KB)
// epilogue writes IN PLACE into act (safe: all reads done at post-gemm barrier);
// weights for stage s+1 prefetched via cp.async under gemm of stage s.
#define FUS_SMEM (6 * 32768)
__global__ void __launch_bounds__(512, 1)
k_fused(const float* __restrict__ A, const float* __restrict__ bv,
        const float* __restrict__ bo, float* __restrict__ out, int n) {
    extern __shared__ char smem[];
    const uint32_t sb = smem_u32(smem);
    const int tid = threadIdx.x, lane = tid & 31, wid = tid >> 5;
    const int wm = wid & 3, wn = wid >> 2;
    const int rowBase = blockIdx.x * 128;

    const int woffs[4] = {49152, 65536, 81920, 98304};
    const float* biases[4] = {bv, bo, bv + HID, bo + HID};

    // prefetch W0 + initial act stage (BN#1 + relu on y2)
    stage_w_async(g_BtH + woffs[0], g_BtL + woffs[0], 128, 0, sb + 65536, sb + 98304, tid);
    CP_COMMIT();
    stage_act<1>(A, 128, 0, rowBase, n, smem, smem + 32768, 1, tid);
    CP_WAIT0();
    __syncthreads();

    float mk[2][2];
#pragma unroll
    for (int t = 0; t < 2; t++)
#pragma unroll
        for (int h = 0; h < 2; h++) {
            int row = rowBase + wm * 32 + t * 16 + h * 8 + (lane >> 2);
            mk[t][h] = (row < n) ? g_mask[row] : 0.f;
        }

    for (int s = 0; s < 4; s++) {
        const uint32_t wb = sb + 65536u + (uint32_t)(s & 1) * 65536u;
        if (s < 3) {
            uint32_t wbn = sb + 65536u + (uint32_t)((s + 1) & 1) * 65536u;
            stage_w_async(g_BtH + woffs[s + 1], g_BtL + woffs[s + 1], 128, 0, wbn,
                          wbn + 32768u, tid);
            CP_COMMIT();
        }

        float acc[2][4][4];
#pragma unroll
        for (int t = 0; t < 2; t++)
#pragma unroll
            for (int nt = 0; nt < 4; nt++)
#pragma unroll
                for (int j = 0; j < 4; j++) acc[t][nt][j] = 0.f;

        gemm_tile(sb, sb + 32768, wb, wb + 32768, acc, wm, wn, lane);
        __syncthreads();  // all reads of act done -> safe to overwrite in place

        const float* bias = biases[s];
        const bool isMask = (s & 1) == 0;
        const bool last = (s == 3);
        const int colb = wn * 32 + (lane & 3) * 2;
#pragma unroll
        for (int nt = 0; nt < 4; nt++) {
            int cc = colb + nt * 8;
            float bx = bias[cc], by = bias[cc + 1];
#pragma unroll
            for (int t = 0; t < 2; t++) {
#pragma unroll
                for (int h = 0; h < 2; h++) {
                    float y0 = acc[t][nt][h * 2] + bx;
                    float y1 = acc[t][nt][h * 2 + 1] + by;
                    if (isMask) {
                        y0 *= mk[t][h];
                        y1 *= mk[t][h];
                    } else {
                        y0 = fmaxf(y0, 0.f);
                        y1 = fmaxf(y1, 0.f);
                    }
                    int rl = wm * 32 + t * 16 + h * 8 + (lane >> 2);
                    if (last) {
                        int row = rowBase + rl;
                        if (row < n)
                            *(float2*)(out + (size_t)row * HID + cc) = make_float2(y0, y1);
                    } else {
                        __nv_bfloat16 h0 = __float2bfloat16_rn(y0);
                        __nv_bfloat16 h1 = __float2bfloat16_rn(y1);
                        uint32_t hi = pack_bf2(h0, h1);
                        uint32_t lo = pack_bf2(
                            __float2bfloat16_rn(y0 - __bfloat162float(h0)),
                            __float2bfloat16_rn(y1 - __bfloat162float(h1)));
                        uint32_t so = swzb(rl, cc * 2);
                        *(uint32_t*)(smem + so) = hi;
                        *(uint32_t*)(smem + 32768 + so) = lo;
                    }
                }
            }
        }
        if (!last) {
            CP_WAIT0();
            __syncthreads();  // epilogue visible + next weights ready
        }
    }
}

// ---------------- launch ----------------
extern "C" void kernel_launch(void* const* d_in, const int* in_sizes, int n_in,
                              void* d_out, int out_size) {
    const float* x   = (const float*)d_in[0];
    const int*   ei  = (const int*)d_in[1];
    const float* W1  = (const float*)d_in[2];
    const float* b1  = (const float*)d_in[3];
    const float* g1  = (const float*)d_in[4];
    const float* be1 = (const float*)d_in[5];
    const float* W2  = (const float*)d_in[6];
    const float* b2  = (const float*)d_in[7];
    const float* g2  = (const float*)d_in[8];
    const float* be2 = (const float*)d_in[9];
    // d_in[10..13] = Wq,bq,Wk,bk : mathematically unused (softmax over dst sums to 1)
    const float* Wv  = (const float*)d_in[14];
    const float* bv  = (const float*)d_in[15];
    const float* Wo  = (const float*)d_in[16];
    const float* bo  = (const float*)d_in[17];
    float* out = (float*)d_out;

    const int n = in_sizes[0] / 256;
    const int E = in_sizes[1] / 2;
    const int* dst = ei + E;

    float *bufA, *bufB, *mask;
    cudaGetSymbolAddress((void**)&bufA, g_bufA);
    cudaGetSymbolAddress((void**)&bufB, g_bufB);
    cudaGetSymbolAddress((void**)&mask, g_mask);

    cudaFuncSetAttribute(k_enc<2, 0>, cudaFuncAttributeMaxDynamicSharedMemorySize, ENC_SMEM);
    cudaFuncSetAttribute(k_enc<1, 1>, cudaFuncAttributeMaxDynamicSharedMemorySize, ENC_SMEM);
    cudaFuncSetAttribute(k_fused, cudaFuncAttributeMaxDynamicSharedMemorySize, FUS_SMEM);

    const int gblk = (n + 127) / 128;

    k_prep<<<dim3(128, 6), 256>>>(W1, W2, Wv, Wo);
    k_init<<<(n + 255) / 256, 256>>>(mask, n);
    k_scatter<<<(E + 255) / 256, 256>>>(dst, E, mask);

    // encoder layer 1: y1 = x @ W1 + b1 (stats fused) -> BN #0
    k_enc<2, 0><<<gblk, 512, ENC_SMEM>>>(x, 0, b1, bufA, n, 0);
    k_finalize<<<1, 128>>>(g1, be1, 0, n);

    // encoder layer 2: y2 = relu(bn0(y1)) @ W2 + b2 (stats fused) -> BN #1
    k_enc<1, 1><<<gblk, 512, ENC_SMEM>>>(bufA, 32768, b2, bufB, n, 0);
    k_finalize<<<1, 128>>>(g2, be2, 1, n);

    // fused attention stack (Wv0/mask -> Wo0/relu -> Wv1/mask -> Wo1/relu)
    k_fused<<<gblk, 512, FUS_SMEM>>>(bufB, bv, bo, out, n);
}

// round 11
// speedup vs baseline: 2.1077x; 1.1095x over previous
#include <cuda_runtime.h>
#include <cuda_bf16.h>
#include <cstdint>

#define NMAX 50000
#define HID 128

// ---------------- scratch ----------------
__device__ __align__(16) float g_bufA[NMAX * HID];
__device__ __align__(16) float g_bufB[NMAX * HID];
__device__ float g_mask[NMAX];
__device__ float g_colsum[HID];
__device__ float g_colsq[HID];
__device__ float g_bnscale[2][HID];
__device__ float g_bnshift[2][HID];
// transposed+split weights ([n][k] bf16): W1T(128x256) then 5x(128x128), hi/lo
__device__ __align__(16) __nv_bfloat16 g_BtH[32768 + 5 * 16384];
__device__ __align__(16) __nv_bfloat16 g_BtL[32768 + 5 * 16384];

// ---------------- helpers ----------------
__device__ __forceinline__ uint32_t smem_u32(const void* p) {
    uint32_t a;
    asm("{ .reg .u64 t; cvta.to.shared.u64 t, %1; cvt.u32.u64 %0, t; }"
        : "=r"(a) : "l"(p));
    return a;
}
__device__ __forceinline__ void ldsm4(uint32_t* r, uint32_t addr) {
    asm volatile("ldmatrix.sync.aligned.m8n8.x4.shared.b16 {%0,%1,%2,%3}, [%4];"
                 : "=r"(r[0]), "=r"(r[1]), "=r"(r[2]), "=r"(r[3]) : "r"(addr));
}
__device__ __forceinline__ void mma16816(float* c, const uint32_t* a, const uint32_t* b) {
    asm volatile(
        "mma.sync.aligned.m16n8k16.row.col.f32.bf16.bf16.f32 "
        "{%0,%1,%2,%3}, {%4,%5,%6,%7}, {%8,%9}, {%0,%1,%2,%3};"
        : "+f"(c[0]), "+f"(c[1]), "+f"(c[2]), "+f"(c[3])
        : "r"(a[0]), "r"(a[1]), "r"(a[2]), "r"(a[3]), "r"(b[0]), "r"(b[1]));
}
__device__ __forceinline__ void cpasync16(uint32_t dst, const void* src) {
    asm volatile("cp.async.cg.shared.global [%0], [%1], 16;" :: "r"(dst), "l"(src));
}
#define CP_COMMIT() asm volatile("cp.async.commit_group;" ::: "memory")
#define CP_WAIT0() asm volatile("cp.async.wait_group 0;" ::: "memory")

__device__ __forceinline__ uint32_t pack_bf2(__nv_bfloat16 a, __nv_bfloat16 b) {
    return ((uint32_t)__bfloat16_as_ushort(b) << 16) | (uint32_t)__bfloat16_as_ushort(a);
}
// XOR-swizzled offset inside a tile with 256B row stride (128 bf16 cols)
__device__ __forceinline__ uint32_t swzb(int r, int kbyte) {
    return (uint32_t)r * 256u + (uint32_t)(kbyte ^ ((r & 7) << 4));
}

// ---------------- small kernels ----------------
__global__ void k_init(float* mask, int n) {
    int i = blockIdx.x * blockDim.x + threadIdx.x;
    if (i < n) mask[i] = 0.f;
    if (i < HID) { g_colsum[i] = 0.f; g_colsq[i] = 0.f; }
}
__global__ void k_scatter(const int* __restrict__ dst, int E, float* __restrict__ mask) {
    int e = blockIdx.x * blockDim.x + threadIdx.x;
    if (e < E) mask[dst[e]] = 1.0f;
}
__global__ void k_finalize(const float* __restrict__ g, const float* __restrict__ beta,
                           int idx, int n) {
    int c = threadIdx.x;
    float inv = 1.0f / (float)n;
    float mean = g_colsum[c] * inv;
    float var = g_colsq[c] * inv - mean * mean;
    float sc = g[c] * rsqrtf(var + 1e-5f);
    g_bnscale[idx][c] = sc;
    g_bnshift[idx][c] = beta[c] - sc * mean;
    g_colsum[c] = 0.f;
    g_colsq[c] = 0.f;
}
// transpose + hi/lo split weights into [n][k] bf16
__global__ void k_prep(const float* __restrict__ W1, const float* __restrict__ W2,
                       const float* __restrict__ Wv, const float* __restrict__ Wo) {
    int m = blockIdx.y;
    const float* src; int K, off;
    switch (m) {
        case 0: src = W1; K = 256; off = 0; break;
        case 1: src = W2; K = 128; off = 32768; break;
        case 2: src = Wv; K = 128; off = 49152; break;
        case 3: src = Wo; K = 128; off = 65536; break;
        case 4: src = Wv + 16384; K = 128; off = 81920; break;
        default: src = Wo + 16384; K = 128; off = 98304; break;
    }
    int idx = blockIdx.x * 256 + threadIdx.x;
    if (idx < K * 128) {
        int k = idx >> 7, nn = idx & 127;
        float v = src[idx];
        __nv_bfloat16 h = __float2bfloat16_rn(v);
        __nv_bfloat16 l = __float2bfloat16_rn(v - __bfloat162float(h));
        g_BtH[off + nn * K + k] = h;
        g_BtL[off + nn * K + k] = l;
    }
}

// ---------------- staging (256 threads, 64-row act tiles) ----------------
__device__ __forceinline__ void split_store(float4 v, int r, int kk, char* dH, char* dL) {
    __nv_bfloat16 h0 = __float2bfloat16_rn(v.x), h1 = __float2bfloat16_rn(v.y);
    __nv_bfloat16 h2 = __float2bfloat16_rn(v.z), h3 = __float2bfloat16_rn(v.w);
    __nv_bfloat16 l0 = __float2bfloat16_rn(v.x - __bfloat162float(h0));
    __nv_bfloat16 l1 = __float2bfloat16_rn(v.y - __bfloat162float(h1));
    __nv_bfloat16 l2 = __float2bfloat16_rn(v.z - __bfloat162float(h2));
    __nv_bfloat16 l3 = __float2bfloat16_rn(v.w - __bfloat162float(h3));
    uint32_t so = swzb(r, kk * 2);
    *(uint2*)(dH + so) = make_uint2(pack_bf2(h0, h1), pack_bf2(h2, h3));
    *(uint2*)(dL + so) = make_uint2(pack_bf2(l0, l1), pack_bf2(l2, l3));
}
template <int PRO>
__device__ __forceinline__ float4 bn_tf(float4 v, int gk, int bnIdx) {
    if (PRO) {
        const float* sc = g_bnscale[bnIdx];
        const float* sh = g_bnshift[bnIdx];
        v.x = fmaxf(fmaf(sc[gk + 0], v.x, sh[gk + 0]), 0.f);
        v.y = fmaxf(fmaf(sc[gk + 1], v.y, sh[gk + 1]), 0.f);
        v.z = fmaxf(fmaf(sc[gk + 2], v.z, sh[gk + 2]), 0.f);
        v.w = fmaxf(fmaf(sc[gk + 3], v.w, sh[gk + 3]), 0.f);
    }
    return v;
}
// 64 rows x 128 cols fp32 -> bf16 hi/lo swizzled (256 threads)
template <int PRO>
__device__ __forceinline__ void stage_act(const float* __restrict__ A, int Kld, int kcol0,
                                          int rowBase, int n, char* dH, char* dL,
                                          int bnIdx, int tid) {
#pragma unroll
    for (int it = 0; it < 8; it++) {
        int f4 = tid + 256 * it;
        int r = f4 >> 5;
        int kk = (f4 & 31) * 4;
        int row = rowBase + r;
        float4 v = make_float4(0.f, 0.f, 0.f, 0.f);
        if (row < n) v = *(const float4*)(A + (size_t)row * Kld + kcol0 + kk);
        v = bn_tf<PRO>(v, kcol0 + kk, bnIdx);
        split_store(v, r, kk, dH, dL);
    }
}
// async weight stage: full 128n x 128k chunk (32KB each hi/lo) via cp.async
// 256 threads x 8 iters x 16B = 32KB per buffer: nr=idx>>4 (0..127 rows),
// kg=(idx&15)*16 (0..240 bytes -> full 256B row)
__device__ __forceinline__ void stage_w_async(const __nv_bfloat16* __restrict__ WH,
                                              const __nv_bfloat16* __restrict__ WL,
                                              int Kw, int k0, uint32_t dH, uint32_t dL,
                                              int tid) {
#pragma unroll
    for (int it = 0; it < 8; it++) {
        int idx = tid + 256 * it;
        int nr = idx >> 4;
        int kg = (idx & 15) * 16;
        uint32_t so = swzb(nr, kg);
        const char* sh_ = (const char*)WH + (size_t)nr * Kw * 2 + k0 * 2 + kg;
        const char* sl_ = (const char*)WL + (size_t)nr * Kw * 2 + k0 * 2 + kg;
        cpasync16(dH + so, sh_);
        cpasync16(dL + so, sl_);
    }
}

// ---------------- warp GEMM: 32x32 per warp, 2x4 warp grid, 3-pass hi/lo ----------
__device__ __forceinline__ void gemm_tile(uint32_t sAH, uint32_t sAL, uint32_t sWH,
                                          uint32_t sWL, float acc[2][4][4], int wm,
                                          int wn, int lane) {
    const uint32_t aBase = (uint32_t)(wm * 32 + (lane & 15)) * 256u;
    const uint32_t aXor = (uint32_t)(((wm * 32 + (lane & 15)) & 7) << 4);
    const int aKb = (lane >> 4) * 16;
    const int nB = wn * 32 + (lane & 7) + ((lane & 16) ? 8 : 0);
    const uint32_t bBase = (uint32_t)nB * 256u;
    const uint32_t bXor = (uint32_t)((nB & 7) << 4);
    const int bKb = (lane & 8) ? 16 : 0;

#pragma unroll
    for (int ks = 0; ks < 8; ks++) {
        const int kb = ks * 32;
        uint32_t Ah[2][4], Al[2][4], Bh[2][4], Bl[2][4];
#pragma unroll
        for (int t = 0; t < 2; t++) {
            uint32_t off = aBase + (uint32_t)t * 4096u + (uint32_t)((kb + aKb) ^ (int)aXor);
            ldsm4(Ah[t], sAH + off);
            ldsm4(Al[t], sAL + off);
        }
#pragma unroll
        for (int g = 0; g < 2; g++) {
            uint32_t off = bBase + (uint32_t)g * 4096u + (uint32_t)((kb + bKb) ^ (int)bXor);
            ldsm4(Bh[g], sWH + off);
            ldsm4(Bl[g], sWL + off);
        }
        // pass-major: consecutive MMAs hit different accumulators
#pragma unroll
        for (int t = 0; t < 2; t++)
#pragma unroll
            for (int nt = 0; nt < 4; nt++)
                mma16816(acc[t][nt], Ah[t], &Bh[nt >> 1][(nt & 1) * 2]);
#pragma unroll
        for (int t = 0; t < 2; t++)
#pragma unroll
            for (int nt = 0; nt < 4; nt++)
                mma16816(acc[t][nt], Ah[t], &Bl[nt >> 1][(nt & 1) * 2]);
#pragma unroll
        for (int t = 0; t < 2; t++)
#pragma unroll
            for (int nt = 0; nt < 4; nt++)
                mma16816(acc[t][nt], Al[t], &Bh[nt >> 1][(nt & 1) * 2]);
    }
}

// ---------------- encoder GEMM kernel (fp32 out + fused BN stats) ----------------
// smem: aH(16K) aL(16K) wH(32K) wL(32K) stats(1K) = 97KB -> 2 CTAs/SM
#define OFF_AL 16384
#define OFF_WH 32768
#define OFF_WL 65536
#define OFF_ST 98304
#define ENC_SMEM (98304 + 1024)
template <int KC, int PRO>
__global__ void __launch_bounds__(256, 2)
k_enc(const float* __restrict__ A, int btOff, const float* __restrict__ bias,
      float* __restrict__ out, int n, int bnIdx) {
    extern __shared__ char smem[];
    char* aH = smem;
    char* aL = smem + OFF_AL;
    float* ssum = (float*)(smem + OFF_ST);
    float* ssq = ssum + 128;
    const uint32_t sb = smem_u32(smem);
    const int tid = threadIdx.x, lane = tid & 31, wid = tid >> 5;
    const int wm = wid & 1, wn = wid >> 1;
    const int rowBase = blockIdx.x * 64;
    const int Kw = KC * 128;
    const __nv_bfloat16* WH = g_BtH + btOff;
    const __nv_bfloat16* WL = g_BtL + btOff;

    if (tid < 128) { ssum[tid] = 0.f; ssq[tid] = 0.f; }

    float acc[2][4][4];
#pragma unroll
    for (int t = 0; t < 2; t++)
#pragma unroll
        for (int nt = 0; nt < 4; nt++)
#pragma unroll
            for (int j = 0; j < 4; j++) acc[t][nt][j] = 0.f;

    // prefetch W chunk0 (async) + stage A chunk0 (direct)
    stage_w_async(WH, WL, Kw, 0, sb + OFF_WH, sb + OFF_WL, tid);
    CP_COMMIT();
    stage_act<PRO>(A, Kw, 0, rowBase, n, aH, aL, bnIdx, tid);
    CP_WAIT0();
    __syncthreads();

    if (KC == 2) {
        // issue A chunk1 global loads early (overlap with gemm of chunk0)
        float4 areg[8];
#pragma unroll
        for (int it = 0; it < 8; it++) {
            int f4 = tid + 256 * it;
            int r = f4 >> 5;
            int kk = (f4 & 31) * 4;
            int row = rowBase + r;
            areg[it] = (row < n) ? *(const float4*)(A + (size_t)row * Kw + 128 + kk)
                                 : make_float4(0.f, 0.f, 0.f, 0.f);
        }
        gemm_tile(sb, sb + OFF_AL, sb + OFF_WH, sb + OFF_WL, acc, wm, wn, lane);
        __syncthreads();  // all reads done -> reuse W/A buffers in place
        stage_w_async(WH, WL, Kw, 128, sb + OFF_WH, sb + OFF_WL, tid);
        CP_COMMIT();
#pragma unroll
        for (int it = 0; it < 8; it++) {
            int f4 = tid + 256 * it;
            int r = f4 >> 5;
            int kk = (f4 & 31) * 4;
            split_store(bn_tf<PRO>(areg[it], 128 + kk, bnIdx), r, kk, aH, aL);
        }
        CP_WAIT0();
        __syncthreads();
        gemm_tile(sb, sb + OFF_AL, sb + OFF_WH, sb + OFF_WL, acc, wm, wn, lane);
    } else {
        gemm_tile(sb, sb + OFF_AL, sb + OFF_WH, sb + OFF_WL, acc, wm, wn, lane);
    }

    // epilogue: bias, store fp32, fused column stats
    const int r0 = rowBase + wm * 32 + (lane >> 2);
    const int colb = wn * 32 + (lane & 3) * 2;
#pragma unroll
    for (int nt = 0; nt < 4; nt++) {
        int cc = colb + nt * 8;
        float bx = bias[cc], by = bias[cc + 1];
        float p0 = 0.f, p1 = 0.f, q0 = 0.f, q1 = 0.f;
#pragma unroll
        for (int t = 0; t < 2; t++) {
#pragma unroll
            for (int h = 0; h < 2; h++) {
                int row = r0 + t * 16 + h * 8;
                float y0 = acc[t][nt][h * 2] + bx;
                float y1 = acc[t][nt][h * 2 + 1] + by;
                if (row < n) {
                    *(float2*)(out + (size_t)row * HID + cc) = make_float2(y0, y1);
                    p0 += y0; q0 += y0 * y0;
                    p1 += y1; q1 += y1 * y1;
                }
            }
        }
#pragma unroll
        for (int m = 4; m <= 16; m <<= 1) {
            p0 += __shfl_xor_sync(~0u, p0, m);
            p1 += __shfl_xor_sync(~0u, p1, m);
            q0 += __shfl_xor_sync(~0u, q0, m);
            q1 += __shfl_xor_sync(~0u, q1, m);
        }
        if ((lane >> 2) == 0) {
            atomicAdd(&ssum[cc], p0);
            atomicAdd(&ssum[cc + 1], p1);
            atomicAdd(&ssq[cc], q0);
            atomicAdd(&ssq[cc + 1], q1);
        }
    }
    __syncthreads();
    if (tid < 128) {
        atomicAdd(&g_colsum[tid], ssum[tid]);
        atomicAdd(&g_colsq[tid], ssq[tid]);
    }
}

// ---------------- fused 4-GEMM attention kernel ----------------
// smem: aH(16K) aL(16K) wH(32K) wL(32K) = 96KB -> 2 CTAs/SM
// single W buffer: next stage's weights cp.async'd after the post-gemm barrier
// (all reads done), overlapping the in-place epilogue.
#define FUS_SMEM 98304
__global__ void __launch_bounds__(256, 2)
k_fused(const float* __restrict__ A, const float* __restrict__ bv,
        const float* __restrict__ bo, float* __restrict__ out, int n) {
    extern __shared__ char smem[];
    const uint32_t sb = smem_u32(smem);
    const int tid = threadIdx.x, lane = tid & 31, wid = tid >> 5;
    const int wm = wid & 1, wn = wid >> 1;
    const int rowBase = blockIdx.x * 64;

    const int woffs[4] = {49152, 65536, 81920, 98304};
    const float* biases[4] = {bv, bo, bv + HID, bo + HID};

    // prefetch W0 + initial act stage (BN#1 + relu on y2)
    stage_w_async(g_BtH + woffs[0], g_BtL + woffs[0], 128, 0, sb + OFF_WH, sb + OFF_WL, tid);
    CP_COMMIT();
    stage_act<1>(A, 128, 0, rowBase, n, smem, smem + OFF_AL, 1, tid);
    CP_WAIT0();
    __syncthreads();

    float mk[2][2];
#pragma unroll
    for (int t = 0; t < 2; t++)
#pragma unroll
        for (int h = 0; h < 2; h++) {
            int row = rowBase + wm * 32 + t * 16 + h * 8 + (lane >> 2);
            mk[t][h] = (row < n) ? g_mask[row] : 0.f;
        }

    for (int s = 0; s < 4; s++) {
        float acc[2][4][4];
#pragma unroll
        for (int t = 0; t < 2; t++)
#pragma unroll
            for (int nt = 0; nt < 4; nt++)
#pragma unroll
                for (int j = 0; j < 4; j++) acc[t][nt][j] = 0.f;

        gemm_tile(sb, sb + OFF_AL, sb + OFF_WH, sb + OFF_WL, acc, wm, wn, lane);
        __syncthreads();  // all reads of act+W done -> safe to overwrite both

        if (s < 3) {
            stage_w_async(g_BtH + woffs[s + 1], g_BtL + woffs[s + 1], 128, 0,
                          sb + OFF_WH, sb + OFF_WL, tid);
            CP_COMMIT();
        }

        const float* bias = biases[s];
        const bool isMask = (s & 1) == 0;
        const bool last = (s == 3);
        const int colb = wn * 32 + (lane & 3) * 2;
#pragma unroll
        for (int nt = 0; nt < 4; nt++) {
            int cc = colb + nt * 8;
            float bx = bias[cc], by = bias[cc + 1];
#pragma unroll
            for (int t = 0; t < 2; t++) {
#pragma unroll
                for (int h = 0; h < 2; h++) {
                    float y0 = acc[t][nt][h * 2] + bx;
                    float y1 = acc[t][nt][h * 2 + 1] + by;
                    if (isMask) {
                        y0 *= mk[t][h];
                        y1 *= mk[t][h];
                    } else {
                        y0 = fmaxf(y0, 0.f);
                        y1 = fmaxf(y1, 0.f);
                    }
                    int rl = wm * 32 + t * 16 + h * 8 + (lane >> 2);
                    if (last) {
                        int row = rowBase + rl;
                        if (row < n)
                            *(float2*)(out + (size_t)row * HID + cc) = make_float2(y0, y1);
                    } else {
                        __nv_bfloat16 h0 = __float2bfloat16_rn(y0);
                        __nv_bfloat16 h1 = __float2bfloat16_rn(y1);
                        uint32_t hi = pack_bf2(h0, h1);
                        uint32_t lo = pack_bf2(
                            __float2bfloat16_rn(y0 - __bfloat162float(h0)),
                            __float2bfloat16_rn(y1 - __bfloat162float(h1)));
                        uint32_t so = swzb(rl, cc * 2);
                        *(uint32_t*)(smem + so) = hi;
                        *(uint32_t*)(smem + OFF_AL + so) = lo;
                    }
                }
            }
        }
        if (!last) {
            CP_WAIT0();
            __syncthreads();  // epilogue visible + next weights ready
        }
    }
}

// ---------------- launch ----------------
extern "C" void kernel_launch(void* const* d_in, const int* in_sizes, int n_in,
                              void* d_out, int out_size) {
    const float* x   = (const float*)d_in[0];
    const int*   ei  = (const int*)d_in[1];
    const float* W1  = (const float*)d_in[2];
    const float* b1  = (const float*)d_in[3];
    const float* g1  = (const float*)d_in[4];
    const float* be1 = (const float*)d_in[5];
    const float* W2  = (const float*)d_in[6];
    const float* b2  = (const float*)d_in[7];
    const float* g2  = (const float*)d_in[8];
    const float* be2 = (const float*)d_in[9];
    // d_in[10..13] = Wq,bq,Wk,bk : mathematically unused (softmax over dst sums to 1)
    const float* Wv  = (const float*)d_in[14];
    const float* bv  = (const float*)d_in[15];
    const float* Wo  = (const float*)d_in[16];
    const float* bo  = (const float*)d_in[17];
    float* out = (float*)d_out;

    const int n = in_sizes[0] / 256;
    const int E = in_sizes[1] / 2;
    const int* dst = ei + E;

    float *bufA, *bufB, *mask;
    cudaGetSymbolAddress((void**)&bufA, g_bufA);
    cudaGetSymbolAddress((void**)&bufB, g_bufB);
    cudaGetSymbolAddress((void**)&mask, g_mask);

    cudaFuncSetAttribute(k_enc<2, 0>, cudaFuncAttributeMaxDynamicSharedMemorySize, ENC_SMEM);
    cudaFuncSetAttribute(k_enc<1, 1>, cudaFuncAttributeMaxDynamicSharedMemorySize, ENC_SMEM);
    cudaFuncSetAttribute(k_fused, cudaFuncAttributeMaxDynamicSharedMemorySize, FUS_SMEM);

    const int gblk = (n + 63) / 64;

    k_prep<<<dim3(128, 6), 256>>>(W1, W2, Wv, Wo);
    k_init<<<(n + 255) / 256, 256>>>(mask, n);
    k_scatter<<<(E + 255) / 256, 256>>>(dst, E, mask);

    // encoder layer 1: y1 = x @ W1 + b1 (stats fused) -> BN #0
    k_enc<2, 0><<<gblk, 256, ENC_SMEM>>>(x, 0, b1, bufA, n, 0);
    k_finalize<<<1, 128>>>(g1, be1, 0, n);

    // encoder layer 2: y2 = relu(bn0(y1)) @ W2 + b2 (stats fused) -> BN #1
    k_enc<1, 1><<<gblk, 256, ENC_SMEM>>>(bufA, 32768, b2, bufB, n, 0);
    k_finalize<<<1, 128>>>(g2, be2, 1, n);

    // fused attention stack (Wv0/mask -> Wo0/relu -> Wv1/mask -> Wo1/relu)
    k_fused<<<gblk, 256, FUS_SMEM>>>(bufB, bv, bo, out, n);
}

// round 12
// speedup vs baseline: 2.6059x; 1.2363x over previous
#include <cuda_runtime.h>
#include <cuda_bf16.h>
#include <cuda_fp16.h>
#include <cstdint>

#define NMAX 50000
#define HID 128

// ---------------- scratch ----------------
__device__ __align__(16) float g_bufA[NMAX * HID];
__device__ __align__(16) float g_bufB[NMAX * HID];
__device__ float g_mask[NMAX];
__device__ float g_colsum[HID];
__device__ float g_colsq[HID];
__device__ float g_bnscale[2][HID];
__device__ float g_bnshift[2][HID];
// transposed weights ([n][k] fp16, single rounded copy): W1T(128x256) then 5x(128x128)
__device__ __align__(16) __half g_Bt16[32768 + 5 * 16384];

// ---------------- helpers ----------------
__device__ __forceinline__ uint32_t smem_u32(const void* p) {
    uint32_t a;
    asm("{ .reg .u64 t; cvta.to.shared.u64 t, %1; cvt.u32.u64 %0, t; }"
        : "=r"(a) : "l"(p));
    return a;
}
__device__ __forceinline__ void ldsm4(uint32_t* r, uint32_t addr) {
    asm volatile("ldmatrix.sync.aligned.m8n8.x4.shared.b16 {%0,%1,%2,%3}, [%4];"
                 : "=r"(r[0]), "=r"(r[1]), "=r"(r[2]), "=r"(r[3]) : "r"(addr));
}
__device__ __forceinline__ void mma16816(float* c, const uint32_t* a, const uint32_t* b) {
    asm volatile(
        "mma.sync.aligned.m16n8k16.row.col.f32.f16.f16.f32 "
        "{%0,%1,%2,%3}, {%4,%5,%6,%7}, {%8,%9}, {%0,%1,%2,%3};"
        : "+f"(c[0]), "+f"(c[1]), "+f"(c[2]), "+f"(c[3])
        : "r"(a[0]), "r"(a[1]), "r"(a[2]), "r"(a[3]), "r"(b[0]), "r"(b[1]));
}
__device__ __forceinline__ void cpasync16(uint32_t dst, const void* src) {
    asm volatile("cp.async.cg.shared.global [%0], [%1], 16;" :: "r"(dst), "l"(src));
}
#define CP_COMMIT() asm volatile("cp.async.commit_group;" ::: "memory")
#define CP_WAIT0() asm volatile("cp.async.wait_group 0;" ::: "memory")

__device__ __forceinline__ uint32_t pack_h2(__half a, __half b) {
    return ((uint32_t)__half_as_ushort(b) << 16) | (uint32_t)__half_as_ushort(a);
}
// XOR-swizzled offset inside a tile with 256B row stride (128 fp16 cols)
__device__ __forceinline__ uint32_t swzb(int r, int kbyte) {
    return (uint32_t)r * 256u + (uint32_t)(kbyte ^ ((r & 7) << 4));
}

// ---------------- small kernels ----------------
__global__ void k_init(float* mask, int n) {
    int i = blockIdx.x * blockDim.x + threadIdx.x;
    if (i < n) mask[i] = 0.f;
    if (i < HID) { g_colsum[i] = 0.f; g_colsq[i] = 0.f; }
}
__global__ void k_scatter(const int* __restrict__ dst, int E, float* __restrict__ mask) {
    int e = blockIdx.x * blockDim.x + threadIdx.x;
    if (e < E) mask[dst[e]] = 1.0f;
}
__global__ void k_finalize(const float* __restrict__ g, const float* __restrict__ beta,
                           int idx, int n) {
    int c = threadIdx.x;
    float inv = 1.0f / (float)n;
    float mean = g_colsum[c] * inv;
    float var = g_colsq[c] * inv - mean * mean;
    float sc = g[c] * rsqrtf(var + 1e-5f);
    g_bnscale[idx][c] = sc;
    g_bnshift[idx][c] = beta[c] - sc * mean;
    g_colsum[c] = 0.f;
    g_colsq[c] = 0.f;
}
// transpose weights into [n][k] fp16 (single rounded copy)
__global__ void k_prep(const float* __restrict__ W1, const float* __restrict__ W2,
                       const float* __restrict__ Wv, const float* __restrict__ Wo) {
    int m = blockIdx.y;
    const float* src; int K, off;
    switch (m) {
        case 0: src = W1; K = 256; off = 0; break;
        case 1: src = W2; K = 128; off = 32768; break;
        case 2: src = Wv; K = 128; off = 49152; break;
        case 3: src = Wo; K = 128; off = 65536; break;
        case 4: src = Wv + 16384; K = 128; off = 81920; break;
        default: src = Wo + 16384; K = 128; off = 98304; break;
    }
    int idx = blockIdx.x * 256 + threadIdx.x;
    if (idx < K * 128) {
        int k = idx >> 7, nn = idx & 127;
        g_Bt16[off + nn * K + k] = __float2half_rn(src[idx]);
    }
}

// ---------------- staging (256 threads, 64-row act tiles) ----------------
// exact fp16 hi/lo split of fp32 activations
__device__ __forceinline__ void split_store(float4 v, int r, int kk, char* dH, char* dL) {
    __half h0 = __float2half_rn(v.x), h1 = __float2half_rn(v.y);
    __half h2 = __float2half_rn(v.z), h3 = __float2half_rn(v.w);
    __half l0 = __float2half_rn(v.x - __half2float(h0));
    __half l1 = __float2half_rn(v.y - __half2float(h1));
    __half l2 = __float2half_rn(v.z - __half2float(h2));
    __half l3 = __float2half_rn(v.w - __half2float(h3));
    uint32_t so = swzb(r, kk * 2);
    *(uint2*)(dH + so) = make_uint2(pack_h2(h0, h1), pack_h2(h2, h3));
    *(uint2*)(dL + so) = make_uint2(pack_h2(l0, l1), pack_h2(l2, l3));
}
template <int PRO>
__device__ __forceinline__ float4 bn_tf(float4 v, int gk, int bnIdx) {
    if (PRO) {
        const float* sc = g_bnscale[bnIdx];
        const float* sh = g_bnshift[bnIdx];
        v.x = fmaxf(fmaf(sc[gk + 0], v.x, sh[gk + 0]), 0.f);
        v.y = fmaxf(fmaf(sc[gk + 1], v.y, sh[gk + 1]), 0.f);
        v.z = fmaxf(fmaf(sc[gk + 2], v.z, sh[gk + 2]), 0.f);
        v.w = fmaxf(fmaf(sc[gk + 3], v.w, sh[gk + 3]), 0.f);
    }
    return v;
}
// 64 rows x 128 cols fp32 -> fp16 hi/lo swizzled (256 threads)
template <int PRO>
__device__ __forceinline__ void stage_act(const float* __restrict__ A, int Kld, int kcol0,
                                          int rowBase, int n, char* dH, char* dL,
                                          int bnIdx, int tid) {
#pragma unroll
    for (int it = 0; it < 8; it++) {
        int f4 = tid + 256 * it;
        int r = f4 >> 5;
        int kk = (f4 & 31) * 4;
        int row = rowBase + r;
        float4 v = make_float4(0.f, 0.f, 0.f, 0.f);
        if (row < n) v = *(const float4*)(A + (size_t)row * Kld + kcol0 + kk);
        v = bn_tf<PRO>(v, kcol0 + kk, bnIdx);
        split_store(v, r, kk, dH, dL);
    }
}
// async weight stage: full 128n x 128k fp16 chunk (32KB) via cp.async
__device__ __forceinline__ void stage_w_async(const __half* __restrict__ W, int Kw,
                                              int k0, uint32_t dW, int tid) {
#pragma unroll
    for (int it = 0; it < 8; it++) {
        int idx = tid + 256 * it;
        int nr = idx >> 4;
        int kg = (idx & 15) * 16;
        uint32_t so = swzb(nr, kg);
        cpasync16(dW + so, (const char*)W + (size_t)nr * Kw * 2 + k0 * 2 + kg);
    }
}

// ---------------- warp GEMM: 32x32 per warp, 2x4 warp grid, 2-pass A-hi/lo ----------
__device__ __forceinline__ void gemm_tile(uint32_t sAH, uint32_t sAL, uint32_t sW,
                                          float acc[2][4][4], int wm, int wn, int lane) {
    const uint32_t aBase = (uint32_t)(wm * 32 + (lane & 15)) * 256u;
    const uint32_t aXor = (uint32_t)(((wm * 32 + (lane & 15)) & 7) << 4);
    const int aKb = (lane >> 4) * 16;
    const int nB = wn * 32 + (lane & 7) + ((lane & 16) ? 8 : 0);
    const uint32_t bBase = (uint32_t)nB * 256u;
    const uint32_t bXor = (uint32_t)((nB & 7) << 4);
    const int bKb = (lane & 8) ? 16 : 0;

#pragma unroll
    for (int ks = 0; ks < 8; ks++) {
        const int kb = ks * 32;
        uint32_t Ah[2][4], Al[2][4], Bh[2][4];
#pragma unroll
        for (int t = 0; t < 2; t++) {
            uint32_t off = aBase + (uint32_t)t * 4096u + (uint32_t)((kb + aKb) ^ (int)aXor);
            ldsm4(Ah[t], sAH + off);
            ldsm4(Al[t], sAL + off);
        }
#pragma unroll
        for (int g = 0; g < 2; g++) {
            uint32_t off = bBase + (uint32_t)g * 4096u + (uint32_t)((kb + bKb) ^ (int)bXor);
            ldsm4(Bh[g], sW + off);
        }
        // pass-major: consecutive MMAs hit different accumulators
#pragma unroll
        for (int t = 0; t < 2; t++)
#pragma unroll
            for (int nt = 0; nt < 4; nt++)
                mma16816(acc[t][nt], Ah[t], &Bh[nt >> 1][(nt & 1) * 2]);
#pragma unroll
        for (int t = 0; t < 2; t++)
#pragma unroll
            for (int nt = 0; nt < 4; nt++)
                mma16816(acc[t][nt], Al[t], &Bh[nt >> 1][(nt & 1) * 2]);
    }
}

// ---------------- encoder GEMM kernel (fp32 out + fused BN stats) ----------------
// smem: aH(16K) aL(16K) w(32K) stats(1K) = 65KB -> 2-3 CTAs/SM
#define OFF_AL 16384
#define OFF_W 32768
#define OFF_ST 65536
#define ENC_SMEM (65536 + 1024)
template <int KC, int PRO>
__global__ void __launch_bounds__(256, 2)
k_enc(const float* __restrict__ A, int btOff, const float* __restrict__ bias,
      float* __restrict__ out, int n, int bnIdx) {
    extern __shared__ char smem[];
    char* aH = smem;
    char* aL = smem + OFF_AL;
    float* ssum = (float*)(smem + OFF_ST);
    float* ssq = ssum + 128;
    const uint32_t sb = smem_u32(smem);
    const int tid = threadIdx.x, lane = tid & 31, wid = tid >> 5;
    const int wm = wid & 1, wn = wid >> 1;
    const int rowBase = blockIdx.x * 64;
    const int Kw = KC * 128;
    const __half* W = g_Bt16 + btOff;

    if (tid < 128) { ssum[tid] = 0.f; ssq[tid] = 0.f; }

    float acc[2][4][4];
#pragma unroll
    for (int t = 0; t < 2; t++)
#pragma unroll
        for (int nt = 0; nt < 4; nt++)
#pragma unroll
            for (int j = 0; j < 4; j++) acc[t][nt][j] = 0.f;

    // prefetch W chunk0 (async) + stage A chunk0 (direct)
    stage_w_async(W, Kw, 0, sb + OFF_W, tid);
    CP_COMMIT();
    stage_act<PRO>(A, Kw, 0, rowBase, n, aH, aL, bnIdx, tid);
    CP_WAIT0();
    __syncthreads();

    if (KC == 2) {
        // issue A chunk1 global loads early (overlap with gemm of chunk0)
        float4 areg[8];
#pragma unroll
        for (int it = 0; it < 8; it++) {
            int f4 = tid + 256 * it;
            int r = f4 >> 5;
            int kk = (f4 & 31) * 4;
            int row = rowBase + r;
            areg[it] = (row < n) ? *(const float4*)(A + (size_t)row * Kw + 128 + kk)
                                 : make_float4(0.f, 0.f, 0.f, 0.f);
        }
        gemm_tile(sb, sb + OFF_AL, sb + OFF_W, acc, wm, wn, lane);
        __syncthreads();  // all reads done -> reuse W/A buffers in place
        stage_w_async(W, Kw, 128, sb + OFF_W, tid);
        CP_COMMIT();
#pragma unroll
        for (int it = 0; it < 8; it++) {
            int f4 = tid + 256 * it;
            int r = f4 >> 5;
            int kk = (f4 & 31) * 4;
            split_store(bn_tf<PRO>(areg[it], 128 + kk, bnIdx), r, kk, aH, aL);
        }
        CP_WAIT0();
        __syncthreads();
        gemm_tile(sb, sb + OFF_AL, sb + OFF_W, acc, wm, wn, lane);
    } else {
        gemm_tile(sb, sb + OFF_AL, sb + OFF_W, acc, wm, wn, lane);
    }

    // epilogue: bias, store fp32, fused column stats
    const int r0 = rowBase + wm * 32 + (lane >> 2);
    const int colb = wn * 32 + (lane & 3) * 2;
#pragma unroll
    for (int nt = 0; nt < 4; nt++) {
        int cc = colb + nt * 8;
        float bx = bias[cc], by = bias[cc + 1];
        float p0 = 0.f, p1 = 0.f, q0 = 0.f, q1 = 0.f;
#pragma unroll
        for (int t = 0; t < 2; t++) {
#pragma unroll
            for (int h = 0; h < 2; h++) {
                int row = r0 + t * 16 + h * 8;
                float y0 = acc[t][nt][h * 2] + bx;
                float y1 = acc[t][nt][h * 2 + 1] + by;
                if (row < n) {
                    *(float2*)(out + (size_t)row * HID + cc) = make_float2(y0, y1);
                    p0 += y0; q0 += y0 * y0;
                    p1 += y1; q1 += y1 * y1;
                }
            }
        }
#pragma unroll
        for (int m = 4; m <= 16; m <<= 1) {
            p0 += __shfl_xor_sync(~0u, p0, m);
            p1 += __shfl_xor_sync(~0u, p1, m);
            q0 += __shfl_xor_sync(~0u, q0, m);
            q1 += __shfl_xor_sync(~0u, q1, m);
        }
        if ((lane >> 2) == 0) {
            atomicAdd(&ssum[cc], p0);
            atomicAdd(&ssum[cc + 1], p1);
            atomicAdd(&ssq[cc], q0);
            atomicAdd(&ssq[cc + 1], q1);
        }
    }
    __syncthreads();
    if (tid < 128) {
        atomicAdd(&g_colsum[tid], ssum[tid]);
        atomicAdd(&g_colsq[tid], ssq[tid]);
    }
}

// ---------------- fused 4-GEMM attention kernel ----------------
// smem: aH(16K) aL(16K) w(32K) = 64KB -> 3 CTAs/SM (regs capped 85)
#define FUS_SMEM 65536
__global__ void __launch_bounds__(256, 3)
k_fused(const float* __restrict__ A, const float* __restrict__ bv,
        const float* __restrict__ bo, float* __restrict__ out, int n) {
    extern __shared__ char smem[];
    const uint32_t sb = smem_u32(smem);
    const int tid = threadIdx.x, lane = tid & 31, wid = tid >> 5;
    const int wm = wid & 1, wn = wid >> 1;
    const int rowBase = blockIdx.x * 64;

    const int woffs[4] = {49152, 65536, 81920, 98304};
    const float* biases[4] = {bv, bo, bv + HID, bo + HID};

    // prefetch W0 + initial act stage (BN#1 + relu on y2)
    stage_w_async(g_Bt16 + woffs[0], 128, 0, sb + OFF_W, tid);
    CP_COMMIT();
    stage_act<1>(A, 128, 0, rowBase, n, smem, smem + OFF_AL, 1, tid);
    CP_WAIT0();
    __syncthreads();

    float mk[2][2];
#pragma unroll
    for (int t = 0; t < 2; t++)
#pragma unroll
        for (int h = 0; h < 2; h++) {
            int row = rowBase + wm * 32 + t * 16 + h * 8 + (lane >> 2);
            mk[t][h] = (row < n) ? g_mask[row] : 0.f;
        }

    for (int s = 0; s < 4; s++) {
        float acc[2][4][4];
#pragma unroll
        for (int t = 0; t < 2; t++)
#pragma unroll
            for (int nt = 0; nt < 4; nt++)
#pragma unroll
                for (int j = 0; j < 4; j++) acc[t][nt][j] = 0.f;

        gemm_tile(sb, sb + OFF_AL, sb + OFF_W, acc, wm, wn, lane);
        __syncthreads();  // all reads of act+W done -> safe to overwrite both

        if (s < 3) {
            stage_w_async(g_Bt16 + woffs[s + 1], 128, 0, sb + OFF_W, tid);
            CP_COMMIT();
        }

        const float* bias = biases[s];
        const bool isMask = (s & 1) == 0;
        const bool last = (s == 3);
        const int colb = wn * 32 + (lane & 3) * 2;
#pragma unroll
        for (int nt = 0; nt < 4; nt++) {
            int cc = colb + nt * 8;
            float bx = bias[cc], by = bias[cc + 1];
#pragma unroll
            for (int t = 0; t < 2; t++) {
#pragma unroll
                for (int h = 0; h < 2; h++) {
                    float y0 = acc[t][nt][h * 2] + bx;
                    float y1 = acc[t][nt][h * 2 + 1] + by;
                    if (isMask) {
                        y0 *= mk[t][h];
                        y1 *= mk[t][h];
                    } else {
                        y0 = fmaxf(y0, 0.f);
                        y1 = fmaxf(y1, 0.f);
                    }
                    int rl = wm * 32 + t * 16 + h * 8 + (lane >> 2);
                    if (last) {
                        int row = rowBase + rl;
                        if (row < n)
                            *(float2*)(out + (size_t)row * HID + cc) = make_float2(y0, y1);
                    } else {
                        __half h0 = __float2half_rn(y0);
                        __half h1 = __float2half_rn(y1);
                        uint32_t hi = pack_h2(h0, h1);
                        uint32_t lo = pack_h2(__float2half_rn(y0 - __half2float(h0)),
                                              __float2half_rn(y1 - __half2float(h1)));
                        uint32_t so = swzb(rl, cc * 2);
                        *(uint32_t*)(smem + so) = hi;
                        *(uint32_t*)(smem + OFF_AL + so) = lo;
                    }
                }
            }
        }
        if (!last) {
            CP_WAIT0();
            __syncthreads();  // epilogue visible + next weights ready
        }
    }
}

// ---------------- launch ----------------
extern "C" void kernel_launch(void* const* d_in, const int* in_sizes, int n_in,
                              void* d_out, int out_size) {
    const float* x   = (const float*)d_in[0];
    const int*   ei  = (const int*)d_in[1];
    const float* W1  = (const float*)d_in[2];
    const float* b1  = (const float*)d_in[3];
    const float* g1  = (const float*)d_in[4];
    const float* be1 = (const float*)d_in[5];
    const float* W2  = (const float*)d_in[6];
    const float* b2  = (const float*)d_in[7];
    const float* g2  = (const float*)d_in[8];
    const float* be2 = (const float*)d_in[9];
    // d_in[10..13] = Wq,bq,Wk,bk : mathematically unused (softmax over dst sums to 1)
    const float* Wv  = (const float*)d_in[14];
    const float* bv  = (const float*)d_in[15];
    const float* Wo  = (const float*)d_in[16];
    const float* bo  = (const float*)d_in[17];
    float* out = (float*)d_out;

    const int n = in_sizes[0] / 256;
    const int E = in_sizes[1] / 2;
    const int* dst = ei + E;

    float *bufA, *bufB, *mask;
    cudaGetSymbolAddress((void**)&bufA, g_bufA);
    cudaGetSymbolAddress((void**)&bufB, g_bufB);
    cudaGetSymbolAddress((void**)&mask, g_mask);

    cudaFuncSetAttribute(k_enc<2, 0>, cudaFuncAttributeMaxDynamicSharedMemorySize, ENC_SMEM);
    cudaFuncSetAttribute(k_enc<1, 1>, cudaFuncAttributeMaxDynamicSharedMemorySize, ENC_SMEM);
    cudaFuncSetAttribute(k_fused, cudaFuncAttributeMaxDynamicSharedMemorySize, FUS_SMEM);

    const int gblk = (n + 63) / 64;

    k_prep<<<dim3(128, 6), 256>>>(W1, W2, Wv, Wo);
    k_init<<<(n + 255) / 256, 256>>>(mask, n);
    k_scatter<<<(E + 255) / 256, 256>>>(dst, E, mask);

    // encoder layer 1: y1 = x @ W1 + b1 (stats fused) -> BN #0
    k_enc<2, 0><<<gblk, 256, ENC_SMEM>>>(x, 0, b1, bufA, n, 0);
    k_finalize<<<1, 128>>>(g1, be1, 0, n);

    // encoder layer 2: y2 = relu(bn0(y1)) @ W2 + b2 (stats fused) -> BN #1
    k_enc<1, 1><<<gblk, 256, ENC_SMEM>>>(bufA, 32768, b2, bufB, n, 0);
    k_finalize<<<1, 128>>>(g2, be2, 1, n);

    // fused attention stack (Wv0/mask -> Wo0/relu -> Wv1/mask -> Wo1/relu)
    k_fused<<<gblk, 256, FUS_SMEM>>>(bufB, bv, bo, out, n);
}